// round 2
// baseline (speedup 1.0000x reference)
#include <cuda_runtime.h>
#include <math.h>

// Problem constants
#define Bb 32
#define Tt 60
#define Ii 577
#define Hh 768
#define Pp 384
#define Gg 256
#define Cc 128
#define Nn 637   // Ii + Tt

// ---------------------------------------------------------------------------
// Scratch (static __device__ globals; no allocation anywhere)
// ---------------------------------------------------------------------------
__device__ float g_feat_t[(size_t)Bb * Tt * Hh];          // 1.47M
__device__ float g_feat_v[(size_t)Bb * Ii * Hh];          // 14.2M
__device__ float g_x[(size_t)Bb * Nn * Pp];               // 7.8M
__device__ float g_h[(size_t)Bb * Nn * Gg];               // 5.2M
__device__ float g_gat[(size_t)Bb * Nn * Gg];             // 5.2M
__device__ float g_Pmat[(size_t)Bb * Nn * Nn];            // 13.0M (52MB)
__device__ float g_el[Bb * Nn];
__device__ float g_er[Bb * Nn];
__device__ float g_hgi[Bb * Pp];
__device__ float g_hgt[Bb * Pp];
__device__ float g_part[2 * Bb];

// ---------------------------------------------------------------------------
// Generic tiled SGEMM with fused bias + activation + optional row remap.
// C[M,N] = act(A[M,K] @ B[K,N] + bias), batched via blockIdx.z strides.
// rowsPer > 0 remaps output row r -> (r/rowsPer)*Nn + rowOff + r%rowsPer
// (used to scatter proj_v / proj_t into the concatenated x buffer).
// ---------------------------------------------------------------------------
#define BM 64
#define BN 64
#define BK 16

#define ACT_NONE 0
#define ACT_SIG  1
#define ACT_RELU 2
#define ACT_ELU  3

__global__ __launch_bounds__(256) void sgemm_kernel(
    const float* __restrict__ A, const float* __restrict__ Bm,
    const float* __restrict__ bias, float* __restrict__ C,
    int M, int N, int K, int ldc,
    long sA, long sB, long sC,
    int mode, int rowsPer, int rowOff)
{
    A  += (long)blockIdx.z * sA;
    Bm += (long)blockIdx.z * sB;
    C  += (long)blockIdx.z * sC;

    __shared__ float As[BK][BM];
    __shared__ float Bs[BK][BN];

    int tid = threadIdx.x;
    int tx = tid & 15;         // 0..15  -> 4 output cols each
    int ty = tid >> 4;         // 0..15  -> 4 output rows each
    int row0 = blockIdx.y * BM;
    int col0 = blockIdx.x * BN;

    float acc[4][4] = {};

    for (int k0 = 0; k0 < K; k0 += BK) {
        // A tile: BM x BK = 1024 elems, transposed into As[c][r]
        #pragma unroll
        for (int j = 0; j < 4; j++) {
            int i = tid + j * 256;
            int r = i >> 4, c = i & 15;
            int gr = row0 + r, gc = k0 + c;
            As[c][r] = (gr < M && gc < K) ? A[(long)gr * K + gc] : 0.f;
        }
        // B tile: BK x BN = 1024 elems
        #pragma unroll
        for (int j = 0; j < 4; j++) {
            int i = tid + j * 256;
            int r = i >> 6, c = i & 63;
            int gr = k0 + r, gc = col0 + c;
            Bs[r][c] = (gr < K && gc < N) ? Bm[(long)gr * N + gc] : 0.f;
        }
        __syncthreads();

        #pragma unroll
        for (int kk = 0; kk < BK; kk++) {
            float a[4], b[4];
            #pragma unroll
            for (int u = 0; u < 4; u++) a[u] = As[kk][ty * 4 + u];
            #pragma unroll
            for (int u = 0; u < 4; u++) b[u] = Bs[kk][tx * 4 + u];
            #pragma unroll
            for (int u = 0; u < 4; u++)
                #pragma unroll
                for (int v = 0; v < 4; v++)
                    acc[u][v] = fmaf(a[u], b[v], acc[u][v]);
        }
        __syncthreads();
    }

    #pragma unroll
    for (int u = 0; u < 4; u++) {
        int r = row0 + ty * 4 + u;
        if (r >= M) continue;
        long orow = r;
        if (rowsPer > 0) orow = (long)(r / rowsPer) * Nn + rowOff + (r % rowsPer);
        #pragma unroll
        for (int v = 0; v < 4; v++) {
            int c = col0 + tx * 4 + v;
            if (c >= N) continue;
            float val = acc[u][v];
            if (bias) val += bias[c];
            if (mode == ACT_SIG)       val = 1.f / (1.f + expf(-val));
            else if (mode == ACT_RELU) val = fmaxf(val, 0.f);
            else if (mode == ACT_ELU)  val = val > 0.f ? val : expm1f(val);
            C[orow * (long)ldc + c] = val;
        }
    }
}

// ---------------------------------------------------------------------------
// Per-row scores: el[row] = h[row,:] . al,  er[row] = h[row,:] . ar  (G=256)
// ---------------------------------------------------------------------------
__global__ void score_kernel(const float* __restrict__ h,
                             const float* __restrict__ al,
                             const float* __restrict__ ar,
                             float* __restrict__ el, float* __restrict__ er)
{
    int row = blockIdx.x;
    const float* hr = h + (long)row * Gg;
    int t = threadIdx.x;   // 128
    float a = hr[t] * al[t] + hr[t + 128] * al[t + 128];
    float b = hr[t] * ar[t] + hr[t + 128] * ar[t + 128];
    __shared__ float sa[128], sb[128];
    sa[t] = a; sb[t] = b; __syncthreads();
    for (int o = 64; o > 0; o >>= 1) {
        if (t < o) { sa[t] += sa[t + o]; sb[t] += sb[t + o]; }
        __syncthreads();
    }
    if (t == 0) { el[row] = sa[0]; er[row] = sb[0]; }
}

// ---------------------------------------------------------------------------
// Build normalized attention matrix:
// P[b,d,s] = (s==d) ? 0 : exp(lrelu(el[b,s]+er[b,d])) / Z(b,d)
// One block per (b,d) row. Single pass: values kept in registers.
// ---------------------------------------------------------------------------
__global__ void build_p_kernel(const float* __restrict__ el,
                               const float* __restrict__ er,
                               float* __restrict__ Pm)
{
    int row = blockIdx.x;              // b*Nn + d
    int b = row / Nn, d = row % Nn;
    const float* elb = el + b * Nn;
    float erd = er[row];
    float* pr = Pm + (long)row * Nn;
    int t = threadIdx.x;               // 256

    float vals[3];
    float s = 0.f;
    #pragma unroll
    for (int it = 0; it < 3; it++) {
        int sIdx = t + it * 256;
        float v = 0.f;
        if (sIdx < Nn && sIdx != d) {
            float x = elb[sIdx] + erd;
            x = x > 0.f ? x : 0.2f * x;    // leaky relu, slope 0.2
            v = expf(x);
        }
        vals[it] = v;
        s += v;
    }
    __shared__ float red[256];
    red[t] = s; __syncthreads();
    for (int o = 128; o > 0; o >>= 1) {
        if (t < o) red[t] += red[t + o];
        __syncthreads();
    }
    float inv = 1.f / red[0];
    #pragma unroll
    for (int it = 0; it < 3; it++) {
        int sIdx = t + it * 256;
        if (sIdx < Nn) pr[sIdx] = vals[it] * inv;
    }
}

// ---------------------------------------------------------------------------
// Column means of x over rows [rowOff, rowOff+cnt) of each batch sample.
// grid = (Bb, Pp/128), 128 threads.
// ---------------------------------------------------------------------------
__global__ void mean_kernel(const float* __restrict__ x, float* __restrict__ out,
                            int rowOff, int cnt)
{
    int b = blockIdx.x;
    int p = blockIdx.y * 128 + threadIdx.x;
    const float* base = x + ((long)b * Nn + rowOff) * Pp + p;
    float s = 0.f;
    for (int i = 0; i < cnt; i++) s += base[(long)i * Pp];
    out[b * Pp + p] = s / (float)cnt;
}

// ---------------------------------------------------------------------------
// Symmetric KL partial per batch row: part[b] = sum_c exp(lq)(lq-lp),
// part[Bb+b] = sum_c exp(lp)(lp-lq). Exact log-softmax in fp32.
// ---------------------------------------------------------------------------
__global__ void kl_kernel(const float* __restrict__ Pm, long sp,
                          const float* __restrict__ Qm, long sq,
                          int D, float* __restrict__ part)
{
    int b = blockIdx.x;
    const float* p = Pm + b * sp;
    const float* q = Qm + b * sq;
    int t = threadIdx.x;   // 128
    __shared__ float s1[128], s2[128];

    float mp = -1e30f, mq = -1e30f;
    for (int c = t; c < D; c += 128) { mp = fmaxf(mp, p[c]); mq = fmaxf(mq, q[c]); }
    s1[t] = mp; s2[t] = mq; __syncthreads();
    for (int o = 64; o > 0; o >>= 1) {
        if (t < o) { s1[t] = fmaxf(s1[t], s1[t + o]); s2[t] = fmaxf(s2[t], s2[t + o]); }
        __syncthreads();
    }
    float MP = s1[0], MQ = s2[0];
    __syncthreads();

    float ssp = 0.f, ssq = 0.f;
    for (int c = t; c < D; c += 128) { ssp += expf(p[c] - MP); ssq += expf(q[c] - MQ); }
    s1[t] = ssp; s2[t] = ssq; __syncthreads();
    for (int o = 64; o > 0; o >>= 1) {
        if (t < o) { s1[t] += s1[t + o]; s2[t] += s2[t + o]; }
        __syncthreads();
    }
    float lsep = MP + logf(s1[0]);
    float lseq = MQ + logf(s2[0]);
    __syncthreads();

    float kpq = 0.f, kqp = 0.f;
    for (int c = t; c < D; c += 128) {
        float lp = p[c] - lsep, lq = q[c] - lseq;
        kpq += expf(lq) * (lq - lp);
        kqp += expf(lp) * (lp - lq);
    }
    s1[t] = kpq; s2[t] = kqp; __syncthreads();
    for (int o = 64; o > 0; o >>= 1) {
        if (t < o) { s1[t] += s1[t + o]; s2[t] += s2[t + o]; }
        __syncthreads();
    }
    if (t == 0) { part[b] = s1[0]; part[Bb + b] = s2[0]; }
}

__global__ void kl_final(const float* __restrict__ part, float* __restrict__ out)
{
    int t = threadIdx.x;   // 32
    float a = part[t], b = part[Bb + t];
    for (int o = 16; o > 0; o >>= 1) {
        a += __shfl_down_sync(0xffffffff, a, o);
        b += __shfl_down_sync(0xffffffff, b, o);
    }
    if (t == 0) out[0] = 0.5f * (a + b);
}

// ---------------------------------------------------------------------------
// Host launch
// ---------------------------------------------------------------------------
static inline void launch_gemm(const float* A, const float* B, const float* bias,
                               float* C, int M, int N, int K, int ldc,
                               long sA, long sB, long sC, int batches,
                               int mode, int rowsPer, int rowOff)
{
    dim3 grid((N + BN - 1) / BN, (M + BM - 1) / BM, batches);
    sgemm_kernel<<<grid, 256>>>(A, B, bias, C, M, N, K, ldc, sA, sB, sC,
                                mode, rowsPer, rowOff);
}

extern "C" void kernel_launch(void* const* d_in, const int* in_sizes, int n_in,
                              void* d_out, int out_size)
{
    const float* utt_t = (const float*)d_in[0];
    const float* utt_v = (const float*)d_in[1];
    const float* Wpt   = (const float*)d_in[2];
    const float* bpt   = (const float*)d_in[3];
    const float* Wpv   = (const float*)d_in[4];
    const float* bpv   = (const float*)d_in[5];
    const float* Ws    = (const float*)d_in[6];
    const float* bs    = (const float*)d_in[7];
    const float* Wproj = (const float*)d_in[8];
    const float* bproj = (const float*)d_in[9];
    const float* Wg    = (const float*)d_in[10];
    const float* al    = (const float*)d_in[11];
    const float* ar    = (const float*)d_in[12];
    const float* Wc    = (const float*)d_in[13];
    const float* bc    = (const float*)d_in[14];
    float* out = (float*)d_out;

    float *ft, *fv, *x, *h, *gat, *Pm, *el, *er, *hgi, *hgt, *part;
    cudaGetSymbolAddress((void**)&ft,  g_feat_t);
    cudaGetSymbolAddress((void**)&fv,  g_feat_v);
    cudaGetSymbolAddress((void**)&x,   g_x);
    cudaGetSymbolAddress((void**)&h,   g_h);
    cudaGetSymbolAddress((void**)&gat, g_gat);
    cudaGetSymbolAddress((void**)&Pm,  g_Pmat);
    cudaGetSymbolAddress((void**)&el,  g_el);
    cudaGetSymbolAddress((void**)&er,  g_er);
    cudaGetSymbolAddress((void**)&hgi, g_hgi);
    cudaGetSymbolAddress((void**)&hgt, g_hgt);
    cudaGetSymbolAddress((void**)&part,g_part);

    const long EMB = (long)Bb * Nn * Cc;

    for (int branch = 0; branch < 2; branch++) {
        const float* Wt = (branch == 0) ? Wpt : Ws;
        const float* bt = (branch == 0) ? bpt : bs;
        const float* Wv = (branch == 0) ? Wpv : Ws;
        const float* bv = (branch == 0) ? bpv : bs;
        float* emb_out = out + (branch == 0 ? 0 : EMB);

        // sigmoid projections
        launch_gemm(utt_t, Wt, bt, ft, Bb * Tt, Hh, Hh, Hh, 0, 0, 0, 1, ACT_SIG, 0, 0);
        launch_gemm(utt_v, Wv, bv, fv, Bb * Ii, Hh, Hh, Hh, 0, 0, 0, 1, ACT_SIG, 0, 0);

        // relu projection into concatenated x: rows [0,I) = v, [I,N) = t
        launch_gemm(fv, Wproj, bproj, x, Bb * Ii, Pp, Hh, Pp, 0, 0, 0, 1, ACT_RELU, Ii, 0);
        launch_gemm(ft, Wproj, bproj, x, Bb * Tt, Pp, Hh, Pp, 0, 0, 0, 1, ACT_RELU, Tt, Ii);

        if (branch == 1) {
            // readout means for share_loss (before x is reused next branch — it isn't, but safe)
            mean_kernel<<<dim3(Bb, Pp / 128), 128>>>(x, hgi, 0, Ii);
            mean_kernel<<<dim3(Bb, Pp / 128), 128>>>(x, hgt, Ii, Tt);
        }

        // GAT: h = x @ Wg
        launch_gemm(x, Wg, nullptr, h, Bb * Nn, Gg, Pp, Gg, 0, 0, 0, 1, ACT_NONE, 0, 0);
        // el/er scores
        score_kernel<<<Bb * Nn, 128>>>(h, al, ar, el, er);
        // normalized softmax attention matrix (diag excluded)
        build_p_kernel<<<Bb * Nn, 256>>>(el, er, Pm);
        // batched: gat = elu(P @ h)
        launch_gemm(Pm, h, nullptr, gat, Nn, Gg, Nn, Gg,
                    (long)Nn * Nn, (long)Nn * Gg, (long)Nn * Gg, Bb, ACT_ELU, 0, 0);
        // emb = gat @ Wc + bc  -> directly into output
        launch_gemm(gat, Wc, bc, emb_out, Bb * Nn, Cc, Gg, Cc, 0, 0, 0, 1, ACT_NONE, 0, 0);
    }

    // share_loss = sym_kl(hg_i, hg_t) over [B, P]
    kl_kernel<<<Bb, 128>>>(hgi, (long)Pp, hgt, (long)Pp, Pp, part);
    kl_final<<<1, 32>>>(part, out + 2 * EMB);

    // graph_loss = sym_kl(share_emb[:,0,:], private_emb[:,0,:]) over [B, C]
    kl_kernel<<<Bb, 128>>>(out + EMB, (long)Nn * Cc, out, (long)Nn * Cc, Cc, part);
    kl_final<<<1, 32>>>(part, out + 2 * EMB + 1);
}

// round 3
// speedup vs baseline: 1.1922x; 1.1922x over previous
#include <cuda_runtime.h>
#include <math.h>

// Problem constants
#define Bb 32
#define Tt 60
#define Ii 577
#define Hh 768
#define Pp 384
#define Gg 256
#define Cc 128
#define Nn 637    // Ii + Tt
#define NPAD 640  // Nn padded to multiple of 8 for guard-free K loop

// ---------------------------------------------------------------------------
// Scratch (static __device__ globals; no allocation anywhere)
// ---------------------------------------------------------------------------
__device__ float g_feat_t[(size_t)Bb * Tt * Hh];
__device__ float g_feat_v[(size_t)Bb * Ii * Hh];
__device__ float g_x[(size_t)Bb * Nn * Pp];
__device__ float g_h[(size_t)Bb * Nn * Gg];
__device__ float g_gat[(size_t)Bb * Nn * Gg];
__device__ float g_Pmat[(size_t)Bb * Nn * NPAD];   // padded rows (cols 637..639 = 0)
__device__ float g_el[Bb * Nn];
__device__ float g_er[Bb * Nn];
__device__ float g_hgi[Bb * Pp];
__device__ float g_hgt[Bb * Pp];
__device__ float g_part[2 * Bb];

#define ACT_NONE 0
#define ACT_SIG  1
#define ACT_RELU 2
#define ACT_ELU  3

// ---------------------------------------------------------------------------
// 128x128x8 SGEMM, 256 threads, 8x8 micro-tile, float4 loads, double-buffered.
// Requirements: K % 8 == 0, N % 128 == 0, lda/ldb/ldc % 4 == 0.
// Kb = actual valid rows of B (<= K); rows [Kb, K) read as zero.
// rowsPer > 0 remaps output row r -> (r/rowsPer)*Nn + rowOff + r%rowsPer.
// ---------------------------------------------------------------------------
#define BM 128
#define BN 128
#define BK 8

__global__ __launch_bounds__(256, 2) void sgemm128(
    const float* __restrict__ A, const float* __restrict__ Bm,
    const float* __restrict__ bias, float* __restrict__ C,
    int M, int N, int K, int Kb, int lda, int ldb, int ldc,
    long sA, long sB, long sC,
    int mode, int rowsPer, int rowOff)
{
    A  += (long)blockIdx.z * sA;
    Bm += (long)blockIdx.z * sB;
    C  += (long)blockIdx.z * sC;

    __shared__ float As[2][BK][BM];
    __shared__ float Bs[2][BK][BN];

    const int tid  = threadIdx.x;
    const int row0 = blockIdx.y * BM;
    const int col0 = blockIdx.x * BN;

    // loader mapping
    const int arow = tid >> 1;          // 0..127
    const int acol = (tid & 1) << 2;    // 0 or 4
    const int brow = tid >> 5;          // 0..7
    const int bcol = (tid & 31) << 2;   // 0..124

    const bool aValid = (row0 + arow) < M;
    const float* Aptr = A + (long)(row0 + arow) * lda + acol;
    const float* Bptr = Bm + (long)brow * ldb + col0 + bcol;

    // compute mapping
    const int tx = tid & 15;            // col group (8 cols)
    const int ty = tid >> 4;            // row group (8 rows)

    float acc[8][8] = {};
    const float4 z4 = make_float4(0.f, 0.f, 0.f, 0.f);

    const int nTiles = K / BK;

    // prologue: load tile 0
    float4 aReg = aValid ? *(const float4*)(Aptr) : z4;
    float4 bReg = (brow < Kb) ? *(const float4*)(Bptr) : z4;
    As[0][acol + 0][arow] = aReg.x;
    As[0][acol + 1][arow] = aReg.y;
    As[0][acol + 2][arow] = aReg.z;
    As[0][acol + 3][arow] = aReg.w;
    *(float4*)&Bs[0][brow][bcol] = bReg;
    __syncthreads();

    for (int t = 0; t < nTiles; t++) {
        const int cur = t & 1, nxt = cur ^ 1;
        if (t + 1 < nTiles) {
            const int k0 = (t + 1) * BK;
            aReg = aValid ? *(const float4*)(Aptr + k0) : z4;
            bReg = (k0 + brow < Kb) ? *(const float4*)(Bptr + (long)k0 * ldb) : z4;
        }

        #pragma unroll
        for (int kk = 0; kk < BK; kk++) {
            float4 a0 = *(const float4*)&As[cur][kk][ty * 8];
            float4 a1 = *(const float4*)&As[cur][kk][ty * 8 + 4];
            float4 b0 = *(const float4*)&Bs[cur][kk][tx * 8];
            float4 b1 = *(const float4*)&Bs[cur][kk][tx * 8 + 4];
            float av[8] = {a0.x, a0.y, a0.z, a0.w, a1.x, a1.y, a1.z, a1.w};
            float bv[8] = {b0.x, b0.y, b0.z, b0.w, b1.x, b1.y, b1.z, b1.w};
            #pragma unroll
            for (int u = 0; u < 8; u++)
                #pragma unroll
                for (int v = 0; v < 8; v++)
                    acc[u][v] = fmaf(av[u], bv[v], acc[u][v]);
        }

        if (t + 1 < nTiles) {
            As[nxt][acol + 0][arow] = aReg.x;
            As[nxt][acol + 1][arow] = aReg.y;
            As[nxt][acol + 2][arow] = aReg.z;
            As[nxt][acol + 3][arow] = aReg.w;
            *(float4*)&Bs[nxt][brow][bcol] = bReg;
        }
        __syncthreads();
    }

    // epilogue: bias + activation + (optional row remap) + float4 stores
    float bvals[8];
    #pragma unroll
    for (int v = 0; v < 8; v++)
        bvals[v] = bias ? bias[col0 + tx * 8 + v] : 0.f;

    #pragma unroll
    for (int u = 0; u < 8; u++) {
        int r = row0 + ty * 8 + u;
        if (r >= M) continue;
        long orow = r;
        if (rowsPer > 0) orow = (long)(r / rowsPer) * Nn + rowOff + (r % rowsPer);
        float* cp = C + orow * (long)ldc + col0 + tx * 8;
        float vals[8];
        #pragma unroll
        for (int v = 0; v < 8; v++) {
            float val = acc[u][v] + bvals[v];
            if (mode == ACT_SIG)       val = 1.f / (1.f + expf(-val));
            else if (mode == ACT_RELU) val = fmaxf(val, 0.f);
            else if (mode == ACT_ELU)  val = val > 0.f ? val : expm1f(val);
            vals[v] = val;
        }
        *(float4*)(cp)     = make_float4(vals[0], vals[1], vals[2], vals[3]);
        *(float4*)(cp + 4) = make_float4(vals[4], vals[5], vals[6], vals[7]);
    }
}

// ---------------------------------------------------------------------------
// Per-row scores: el[row] = h[row,:] . al,  er[row] = h[row,:] . ar  (G=256)
// ---------------------------------------------------------------------------
__global__ void score_kernel(const float* __restrict__ h,
                             const float* __restrict__ al,
                             const float* __restrict__ ar,
                             float* __restrict__ el, float* __restrict__ er)
{
    int row = blockIdx.x;
    const float* hr = h + (long)row * Gg;
    int t = threadIdx.x;   // 128
    float a = hr[t] * al[t] + hr[t + 128] * al[t + 128];
    float b = hr[t] * ar[t] + hr[t + 128] * ar[t + 128];
    __shared__ float sa[128], sb[128];
    sa[t] = a; sb[t] = b; __syncthreads();
    for (int o = 64; o > 0; o >>= 1) {
        if (t < o) { sa[t] += sa[t + o]; sb[t] += sb[t + o]; }
        __syncthreads();
    }
    if (t == 0) { el[row] = sa[0]; er[row] = sb[0]; }
}

// ---------------------------------------------------------------------------
// Build normalized attention matrix into padded rows (ld = NPAD):
// P[b,d,s] = (s==d || s>=Nn) ? 0 : exp(lrelu(el[b,s]+er[b,d])) / Z(b,d)
// ---------------------------------------------------------------------------
__global__ void build_p_kernel(const float* __restrict__ el,
                               const float* __restrict__ er,
                               float* __restrict__ Pm)
{
    int row = blockIdx.x;              // b*Nn + d
    int b = row / Nn, d = row % Nn;
    const float* elb = el + b * Nn;
    float erd = er[row];
    float* pr = Pm + (long)row * NPAD;
    int t = threadIdx.x;               // 256

    float vals[3];
    float s = 0.f;
    #pragma unroll
    for (int it = 0; it < 3; it++) {
        int sIdx = t + it * 256;
        float v = 0.f;
        if (sIdx < Nn && sIdx != d) {
            float x = elb[sIdx] + erd;
            x = x > 0.f ? x : 0.2f * x;    // leaky relu, slope 0.2
            v = expf(x);
        }
        vals[it] = v;
        s += v;
    }
    __shared__ float red[256];
    red[t] = s; __syncthreads();
    for (int o = 128; o > 0; o >>= 1) {
        if (t < o) red[t] += red[t + o];
        __syncthreads();
    }
    float inv = 1.f / red[0];
    #pragma unroll
    for (int it = 0; it < 3; it++) {
        int sIdx = t + it * 256;
        if (sIdx < NPAD) pr[sIdx] = vals[it] * inv;   // pad cols get 0
    }
}

// ---------------------------------------------------------------------------
// Column means of x over rows [rowOff, rowOff+cnt) of each batch sample.
// ---------------------------------------------------------------------------
__global__ void mean_kernel(const float* __restrict__ x, float* __restrict__ out,
                            int rowOff, int cnt)
{
    int b = blockIdx.x;
    int p = blockIdx.y * 128 + threadIdx.x;
    const float* base = x + ((long)b * Nn + rowOff) * Pp + p;
    float s = 0.f;
    for (int i = 0; i < cnt; i++) s += base[(long)i * Pp];
    out[b * Pp + p] = s / (float)cnt;
}

// ---------------------------------------------------------------------------
// Symmetric KL partials per batch row (exact fp32 log-softmax)
// ---------------------------------------------------------------------------
__global__ void kl_kernel(const float* __restrict__ Pm, long sp,
                          const float* __restrict__ Qm, long sq,
                          int D, float* __restrict__ part)
{
    int b = blockIdx.x;
    const float* p = Pm + b * sp;
    const float* q = Qm + b * sq;
    int t = threadIdx.x;   // 128
    __shared__ float s1[128], s2[128];

    float mp = -1e30f, mq = -1e30f;
    for (int c = t; c < D; c += 128) { mp = fmaxf(mp, p[c]); mq = fmaxf(mq, q[c]); }
    s1[t] = mp; s2[t] = mq; __syncthreads();
    for (int o = 64; o > 0; o >>= 1) {
        if (t < o) { s1[t] = fmaxf(s1[t], s1[t + o]); s2[t] = fmaxf(s2[t], s2[t + o]); }
        __syncthreads();
    }
    float MP = s1[0], MQ = s2[0];
    __syncthreads();

    float ssp = 0.f, ssq = 0.f;
    for (int c = t; c < D; c += 128) { ssp += expf(p[c] - MP); ssq += expf(q[c] - MQ); }
    s1[t] = ssp; s2[t] = ssq; __syncthreads();
    for (int o = 64; o > 0; o >>= 1) {
        if (t < o) { s1[t] += s1[t + o]; s2[t] += s2[t + o]; }
        __syncthreads();
    }
    float lsep = MP + logf(s1[0]);
    float lseq = MQ + logf(s2[0]);
    __syncthreads();

    float kpq = 0.f, kqp = 0.f;
    for (int c = t; c < D; c += 128) {
        float lp = p[c] - lsep, lq = q[c] - lseq;
        kpq += expf(lq) * (lq - lp);
        kqp += expf(lp) * (lp - lq);
    }
    s1[t] = kpq; s2[t] = kqp; __syncthreads();
    for (int o = 64; o > 0; o >>= 1) {
        if (t < o) { s1[t] += s1[t + o]; s2[t] += s2[t + o]; }
        __syncthreads();
    }
    if (t == 0) { part[b] = s1[0]; part[Bb + b] = s2[0]; }
}

__global__ void kl_final(const float* __restrict__ part, float* __restrict__ out)
{
    int t = threadIdx.x;   // 32
    float a = part[t], b = part[Bb + t];
    for (int o = 16; o > 0; o >>= 1) {
        a += __shfl_down_sync(0xffffffff, a, o);
        b += __shfl_down_sync(0xffffffff, b, o);
    }
    if (t == 0) out[0] = 0.5f * (a + b);
}

// ---------------------------------------------------------------------------
// Host launch
// ---------------------------------------------------------------------------
static inline void launch_gemm(const float* A, const float* B, const float* bias,
                               float* C, int M, int N, int K, int Kb,
                               int lda, int ldb, int ldc,
                               long sA, long sB, long sC, int batches,
                               int mode, int rowsPer, int rowOff)
{
    dim3 grid(N / BN, (M + BM - 1) / BM, batches);
    sgemm128<<<grid, 256>>>(A, B, bias, C, M, N, K, Kb, lda, ldb, ldc,
                            sA, sB, sC, mode, rowsPer, rowOff);
}

extern "C" void kernel_launch(void* const* d_in, const int* in_sizes, int n_in,
                              void* d_out, int out_size)
{
    const float* utt_t = (const float*)d_in[0];
    const float* utt_v = (const float*)d_in[1];
    const float* Wpt   = (const float*)d_in[2];
    const float* bpt   = (const float*)d_in[3];
    const float* Wpv   = (const float*)d_in[4];
    const float* bpv   = (const float*)d_in[5];
    const float* Ws    = (const float*)d_in[6];
    const float* bs    = (const float*)d_in[7];
    const float* Wproj = (const float*)d_in[8];
    const float* bproj = (const float*)d_in[9];
    const float* Wg    = (const float*)d_in[10];
    const float* al    = (const float*)d_in[11];
    const float* ar    = (const float*)d_in[12];
    const float* Wc    = (const float*)d_in[13];
    const float* bc    = (const float*)d_in[14];
    float* out = (float*)d_out;

    float *ft, *fv, *x, *h, *gat, *Pm, *el, *er, *hgi, *hgt, *part;
    cudaGetSymbolAddress((void**)&ft,  g_feat_t);
    cudaGetSymbolAddress((void**)&fv,  g_feat_v);
    cudaGetSymbolAddress((void**)&x,   g_x);
    cudaGetSymbolAddress((void**)&h,   g_h);
    cudaGetSymbolAddress((void**)&gat, g_gat);
    cudaGetSymbolAddress((void**)&Pm,  g_Pmat);
    cudaGetSymbolAddress((void**)&el,  g_el);
    cudaGetSymbolAddress((void**)&er,  g_er);
    cudaGetSymbolAddress((void**)&hgi, g_hgi);
    cudaGetSymbolAddress((void**)&hgt, g_hgt);
    cudaGetSymbolAddress((void**)&part,g_part);

    const long EMB = (long)Bb * Nn * Cc;

    for (int branch = 0; branch < 2; branch++) {
        const float* Wt = (branch == 0) ? Wpt : Ws;
        const float* bt = (branch == 0) ? bpt : bs;
        const float* Wv = (branch == 0) ? Wpv : Ws;
        const float* bv = (branch == 0) ? bpv : bs;
        float* emb_out = out + (branch == 0 ? 0 : EMB);

        // sigmoid projections
        launch_gemm(utt_t, Wt, bt, ft, Bb * Tt, Hh, Hh, Hh, Hh, Hh, Hh,
                    0, 0, 0, 1, ACT_SIG, 0, 0);
        launch_gemm(utt_v, Wv, bv, fv, Bb * Ii, Hh, Hh, Hh, Hh, Hh, Hh,
                    0, 0, 0, 1, ACT_SIG, 0, 0);

        // relu projection into concatenated x: rows [0,I) = v, [I,N) = t
        launch_gemm(fv, Wproj, bproj, x, Bb * Ii, Pp, Hh, Hh, Hh, Pp, Pp,
                    0, 0, 0, 1, ACT_RELU, Ii, 0);
        launch_gemm(ft, Wproj, bproj, x, Bb * Tt, Pp, Hh, Hh, Hh, Pp, Pp,
                    0, 0, 0, 1, ACT_RELU, Tt, Ii);

        if (branch == 1) {
            mean_kernel<<<dim3(Bb, Pp / 128), 128>>>(x, hgi, 0, Ii);
            mean_kernel<<<dim3(Bb, Pp / 128), 128>>>(x, hgt, Ii, Tt);
        }

        // GAT: h = x @ Wg
        launch_gemm(x, Wg, nullptr, h, Bb * Nn, Gg, Pp, Pp, Pp, Gg, Gg,
                    0, 0, 0, 1, ACT_NONE, 0, 0);
        // el/er scores
        score_kernel<<<Bb * Nn, 128>>>(h, al, ar, el, er);
        // normalized softmax attention matrix (padded to NPAD cols)
        build_p_kernel<<<Bb * Nn, 256>>>(el, er, Pm);
        // batched: gat = elu(P @ h); K padded to 640, B rows guarded at 637
        launch_gemm(Pm, h, nullptr, gat, Nn, Gg, NPAD, Nn, NPAD, Gg, Gg,
                    (long)Nn * NPAD, (long)Nn * Gg, (long)Nn * Gg, Bb,
                    ACT_ELU, 0, 0);
        // emb = gat @ Wc + bc  -> directly into output
        launch_gemm(gat, Wc, bc, emb_out, Bb * Nn, Cc, Gg, Gg, Gg, Cc, Cc,
                    0, 0, 0, 1, ACT_NONE, 0, 0);
    }

    // share_loss = sym_kl(hg_i, hg_t) over [B, P]
    kl_kernel<<<Bb, 128>>>(hgi, (long)Pp, hgt, (long)Pp, Pp, part);
    kl_final<<<1, 32>>>(part, out + 2 * EMB);

    // graph_loss = sym_kl(share_emb[:,0,:], private_emb[:,0,:]) over [B, C]
    kl_kernel<<<Bb, 128>>>(out + EMB, (long)Nn * Cc, out, (long)Nn * Cc, Cc, part);
    kl_final<<<1, 32>>>(part, out + 2 * EMB + 1);
}

// round 4
// speedup vs baseline: 3.5510x; 2.9786x over previous
#include <cuda_runtime.h>
#include <math.h>
#include <stdint.h>

// Problem constants
#define Bb 32
#define Tt 60
#define Ii 577
#define Hh 768
#define Pp 384
#define Gg 256
#define Cc 128
#define Nn 637    // Ii + Tt
#define NPAD 640  // Nn padded for guard-free K loop

// ---------------------------------------------------------------------------
// Scratch (static __device__ globals; no allocation anywhere)
// ---------------------------------------------------------------------------
__device__ float g_feat_t[(size_t)Bb * Tt * Hh];
__device__ float g_feat_v[(size_t)Bb * Ii * Hh];
__device__ float g_x[(size_t)Bb * Nn * Pp];
__device__ float g_h[(size_t)Bb * Nn * Gg];
__device__ float g_gat[(size_t)Bb * Nn * Gg];
__device__ float g_Pmat[(size_t)Bb * Nn * NPAD];   // pad cols 637..639 = 0
__device__ float g_el[Bb * Nn];
__device__ float g_er[Bb * Nn];
__device__ float g_hgi[Bb * Pp];
__device__ float g_hgt[Bb * Pp];
__device__ float g_part[2 * Bb];

#define ACT_NONE 0
#define ACT_SIG  1
#define ACT_RELU 2
#define ACT_ELU  3

// ---------------------------------------------------------------------------
// TF32 mma.sync GEMM: 128x128x16 block, 256 threads (8 warps, 2x4),
// warp tile 64x32, m16n8k8 fragments, double-buffered smem.
// Requirements: K % 16 == 0, N % 128 == 0, pointers 16B aligned.
// Kb <= K: B rows in [Kb, K) read as zero (K-padding guard).
// rowsPer > 0 remaps output row r -> (r/rowsPer)*Nn + rowOff + r%rowsPer.
// ---------------------------------------------------------------------------
#define BM 128
#define BN 128
#define BK 16
#define LDA (BK + 4)    // 20 floats  -> conflict-free A-frag reads
#define LDB (BN + 8)    // 136 floats -> conflict-free B-frag reads

__device__ __forceinline__ float cvt_tf32(float x) {
    uint32_t u;
    asm("cvt.rna.tf32.f32 %0, %1;" : "=r"(u) : "f"(x));
    return __uint_as_float(u);
}

__device__ __forceinline__ void mma_tf32(float* c, const uint32_t* a, const uint32_t* b) {
    asm volatile(
        "mma.sync.aligned.m16n8k8.row.col.f32.tf32.tf32.f32 "
        "{%0,%1,%2,%3}, {%4,%5,%6,%7}, {%8,%9}, {%0,%1,%2,%3};"
        : "+f"(c[0]), "+f"(c[1]), "+f"(c[2]), "+f"(c[3])
        : "r"(a[0]), "r"(a[1]), "r"(a[2]), "r"(a[3]), "r"(b[0]), "r"(b[1]));
}

__global__ __launch_bounds__(256, 2) void mma_gemm(
    const float* __restrict__ A, const float* __restrict__ Bm,
    const float* __restrict__ bias, float* __restrict__ C,
    int M, int N, int K, int Kb, int lda, int ldb, int ldc,
    long sA, long sB, long sC,
    int mode, int rowsPer, int rowOff)
{
    A  += (long)blockIdx.z * sA;
    Bm += (long)blockIdx.z * sB;
    C  += (long)blockIdx.z * sC;

    __shared__ float As[2][BM][LDA];   // [m][k] row-major, padded
    __shared__ float Bs[2][BK][LDB];   // [k][n] row-major, padded

    const int tid  = threadIdx.x;
    const int lane = tid & 31;
    const int warp = tid >> 5;
    const int wr   = warp >> 2;        // 0..1 -> 64-row slab
    const int wc   = warp & 3;         // 0..3 -> 32-col slab
    const int g    = lane >> 2;        // groupID 0..7
    const int tg   = lane & 3;         // threadID_in_group 0..3

    const int row0 = blockIdx.y * BM;
    const int col0 = blockIdx.x * BN;

    // gmem loader mapping: A -> 2 float4/thread, B -> 2 float4/thread
    const int ar = tid >> 2, ac = (tid & 3) << 2;           // A: row 0..63(+64), col group
    const int br = tid >> 5, bc = (tid & 31) << 2;          // B: row 0..7(+8), col group

    const float4 z4 = make_float4(0.f, 0.f, 0.f, 0.f);
    float acc[4][4][4] = {};

    const int nTiles = K / BK;

    // ---- load tile helper (macro-free, inlined twice) ----
    float4 aR[2], bR[2];
    {
        // tile 0
        #pragma unroll
        for (int i = 0; i < 2; i++) {
            int r = ar + i * 64;
            aR[i] = (row0 + r < M) ? *(const float4*)(A + (long)(row0 + r) * lda + ac) : z4;
            int kr = br + i * 8;
            bR[i] = (kr < Kb) ? *(const float4*)(Bm + (long)kr * ldb + col0 + bc) : z4;
        }
        #pragma unroll
        for (int i = 0; i < 2; i++) {
            float4 v = aR[i];
            v.x = cvt_tf32(v.x); v.y = cvt_tf32(v.y); v.z = cvt_tf32(v.z); v.w = cvt_tf32(v.w);
            *(float4*)&As[0][ar + i * 64][ac] = v;
            float4 w = bR[i];
            w.x = cvt_tf32(w.x); w.y = cvt_tf32(w.y); w.z = cvt_tf32(w.z); w.w = cvt_tf32(w.w);
            *(float4*)&Bs[0][br + i * 8][bc] = w;
        }
    }
    __syncthreads();

    for (int t = 0; t < nTiles; t++) {
        const int cur = t & 1, nxt = cur ^ 1;
        if (t + 1 < nTiles) {
            const int k0 = (t + 1) * BK;
            #pragma unroll
            for (int i = 0; i < 2; i++) {
                int r = ar + i * 64;
                aR[i] = (row0 + r < M) ? *(const float4*)(A + (long)(row0 + r) * lda + k0 + ac) : z4;
                int kr = k0 + br + i * 8;
                bR[i] = (kr < Kb) ? *(const float4*)(Bm + (long)kr * ldb + col0 + bc) : z4;
            }
        }

        #pragma unroll
        for (int ks = 0; ks < 2; ks++) {
            const int k0 = ks * 8;
            uint32_t bf[4][2];
            #pragma unroll
            for (int ni = 0; ni < 4; ni++) {
                int n = wc * 32 + ni * 8 + g;
                bf[ni][0] = __float_as_uint(Bs[cur][k0 + tg][n]);
                bf[ni][1] = __float_as_uint(Bs[cur][k0 + 4 + tg][n]);
            }
            #pragma unroll
            for (int mi = 0; mi < 4; mi++) {
                int m = wr * 64 + mi * 16 + g;
                uint32_t af[4];
                af[0] = __float_as_uint(As[cur][m][k0 + tg]);
                af[1] = __float_as_uint(As[cur][m + 8][k0 + tg]);
                af[2] = __float_as_uint(As[cur][m][k0 + 4 + tg]);
                af[3] = __float_as_uint(As[cur][m + 8][k0 + 4 + tg]);
                #pragma unroll
                for (int ni = 0; ni < 4; ni++)
                    mma_tf32(acc[mi][ni], af, bf[ni]);
            }
        }

        if (t + 1 < nTiles) {
            #pragma unroll
            for (int i = 0; i < 2; i++) {
                float4 v = aR[i];
                v.x = cvt_tf32(v.x); v.y = cvt_tf32(v.y); v.z = cvt_tf32(v.z); v.w = cvt_tf32(v.w);
                *(float4*)&As[nxt][ar + i * 64][ac] = v;
                float4 w = bR[i];
                w.x = cvt_tf32(w.x); w.y = cvt_tf32(w.y); w.z = cvt_tf32(w.z); w.w = cvt_tf32(w.w);
                *(float4*)&Bs[nxt][br + i * 8][bc] = w;
            }
        }
        __syncthreads();
    }

    // ---- epilogue: bias + activation + optional row remap, float2 stores ----
    #pragma unroll
    for (int mi = 0; mi < 4; mi++) {
        #pragma unroll
        for (int half = 0; half < 2; half++) {
            int r = row0 + wr * 64 + mi * 16 + g + half * 8;
            if (r >= M) continue;
            long orow = r;
            if (rowsPer > 0) orow = (long)(r / rowsPer) * Nn + rowOff + (r % rowsPer);
            float* cbase = C + orow * (long)ldc;
            #pragma unroll
            for (int ni = 0; ni < 4; ni++) {
                int col = col0 + wc * 32 + ni * 8 + 2 * tg;
                float v0 = acc[mi][ni][half * 2 + 0];
                float v1 = acc[mi][ni][half * 2 + 1];
                if (bias) { v0 += bias[col]; v1 += bias[col + 1]; }
                if (mode == ACT_SIG) {
                    v0 = 1.f / (1.f + expf(-v0));
                    v1 = 1.f / (1.f + expf(-v1));
                } else if (mode == ACT_RELU) {
                    v0 = fmaxf(v0, 0.f); v1 = fmaxf(v1, 0.f);
                } else if (mode == ACT_ELU) {
                    v0 = v0 > 0.f ? v0 : expm1f(v0);
                    v1 = v1 > 0.f ? v1 : expm1f(v1);
                }
                *(float2*)(cbase + col) = make_float2(v0, v1);
            }
        }
    }
}

// ---------------------------------------------------------------------------
// Per-row scores: el[row] = h[row,:] . al,  er[row] = h[row,:] . ar  (G=256)
// ---------------------------------------------------------------------------
__global__ void score_kernel(const float* __restrict__ h,
                             const float* __restrict__ al,
                             const float* __restrict__ ar,
                             float* __restrict__ el, float* __restrict__ er)
{
    int row = blockIdx.x;
    const float* hr = h + (long)row * Gg;
    int t = threadIdx.x;   // 128
    float a = hr[t] * al[t] + hr[t + 128] * al[t + 128];
    float b = hr[t] * ar[t] + hr[t + 128] * ar[t + 128];
    __shared__ float sa[128], sb[128];
    sa[t] = a; sb[t] = b; __syncthreads();
    for (int o = 64; o > 0; o >>= 1) {
        if (t < o) { sa[t] += sa[t + o]; sb[t] += sb[t + o]; }
        __syncthreads();
    }
    if (t == 0) { el[row] = sa[0]; er[row] = sb[0]; }
}

// ---------------------------------------------------------------------------
// Build normalized attention matrix into padded rows (ld = NPAD)
// ---------------------------------------------------------------------------
__global__ void build_p_kernel(const float* __restrict__ el,
                               const float* __restrict__ er,
                               float* __restrict__ Pm)
{
    int row = blockIdx.x;              // b*Nn + d
    int b = row / Nn, d = row % Nn;
    const float* elb = el + b * Nn;
    float erd = er[row];
    float* pr = Pm + (long)row * NPAD;
    int t = threadIdx.x;               // 256

    float vals[3];
    float s = 0.f;
    #pragma unroll
    for (int it = 0; it < 3; it++) {
        int sIdx = t + it * 256;
        float v = 0.f;
        if (sIdx < Nn && sIdx != d) {
            float x = elb[sIdx] + erd;
            x = x > 0.f ? x : 0.2f * x;    // leaky relu slope 0.2
            v = expf(x);
        }
        vals[it] = v;
        s += v;
    }
    __shared__ float red[256];
    red[t] = s; __syncthreads();
    for (int o = 128; o > 0; o >>= 1) {
        if (t < o) red[t] += red[t + o];
        __syncthreads();
    }
    float inv = 1.f / red[0];
    #pragma unroll
    for (int it = 0; it < 3; it++) {
        int sIdx = t + it * 256;
        if (sIdx < NPAD) pr[sIdx] = vals[it] * inv;   // pad cols get 0
    }
}

// ---------------------------------------------------------------------------
// Column means over rows [rowOff, rowOff+cnt) of each batch sample
// ---------------------------------------------------------------------------
__global__ void mean_kernel(const float* __restrict__ x, float* __restrict__ out,
                            int rowOff, int cnt)
{
    int b = blockIdx.x;
    int p = blockIdx.y * 128 + threadIdx.x;
    const float* base = x + ((long)b * Nn + rowOff) * Pp + p;
    float s = 0.f;
    for (int i = 0; i < cnt; i++) s += base[(long)i * Pp];
    out[b * Pp + p] = s / (float)cnt;
}

// ---------------------------------------------------------------------------
// Symmetric KL partials per batch row (exact fp32 log-softmax)
// ---------------------------------------------------------------------------
__global__ void kl_kernel(const float* __restrict__ Pm, long sp,
                          const float* __restrict__ Qm, long sq,
                          int D, float* __restrict__ part)
{
    int b = blockIdx.x;
    const float* p = Pm + b * sp;
    const float* q = Qm + b * sq;
    int t = threadIdx.x;   // 128
    __shared__ float s1[128], s2[128];

    float mp = -1e30f, mq = -1e30f;
    for (int c = t; c < D; c += 128) { mp = fmaxf(mp, p[c]); mq = fmaxf(mq, q[c]); }
    s1[t] = mp; s2[t] = mq; __syncthreads();
    for (int o = 64; o > 0; o >>= 1) {
        if (t < o) { s1[t] = fmaxf(s1[t], s1[t + o]); s2[t] = fmaxf(s2[t], s2[t + o]); }
        __syncthreads();
    }
    float MP = s1[0], MQ = s2[0];
    __syncthreads();

    float ssp = 0.f, ssq = 0.f;
    for (int c = t; c < D; c += 128) { ssp += expf(p[c] - MP); ssq += expf(q[c] - MQ); }
    s1[t] = ssp; s2[t] = ssq; __syncthreads();
    for (int o = 64; o > 0; o >>= 1) {
        if (t < o) { s1[t] += s1[t + o]; s2[t] += s2[t + o]; }
        __syncthreads();
    }
    float lsep = MP + logf(s1[0]);
    float lseq = MQ + logf(s2[0]);
    __syncthreads();

    float kpq = 0.f, kqp = 0.f;
    for (int c = t; c < D; c += 128) {
        float lp = p[c] - lsep, lq = q[c] - lseq;
        kpq += expf(lq) * (lq - lp);
        kqp += expf(lp) * (lp - lq);
    }
    s1[t] = kpq; s2[t] = kqp; __syncthreads();
    for (int o = 64; o > 0; o >>= 1) {
        if (t < o) { s1[t] += s1[t + o]; s2[t] += s2[t + o]; }
        __syncthreads();
    }
    if (t == 0) { part[b] = s1[0]; part[Bb + b] = s2[0]; }
}

__global__ void kl_final(const float* __restrict__ part, float* __restrict__ out)
{
    int t = threadIdx.x;   // 32
    float a = part[t], b = part[Bb + t];
    for (int o = 16; o > 0; o >>= 1) {
        a += __shfl_down_sync(0xffffffff, a, o);
        b += __shfl_down_sync(0xffffffff, b, o);
    }
    if (t == 0) out[0] = 0.5f * (a + b);
}

// ---------------------------------------------------------------------------
// Host launch
// ---------------------------------------------------------------------------
static inline void launch_gemm(const float* A, const float* B, const float* bias,
                               float* C, int M, int N, int K, int Kb,
                               int lda, int ldb, int ldc,
                               long sA, long sB, long sC, int batches,
                               int mode, int rowsPer, int rowOff)
{
    dim3 grid(N / BN, (M + BM - 1) / BM, batches);
    mma_gemm<<<grid, 256>>>(A, B, bias, C, M, N, K, Kb, lda, ldb, ldc,
                            sA, sB, sC, mode, rowsPer, rowOff);
}

extern "C" void kernel_launch(void* const* d_in, const int* in_sizes, int n_in,
                              void* d_out, int out_size)
{
    const float* utt_t = (const float*)d_in[0];
    const float* utt_v = (const float*)d_in[1];
    const float* Wpt   = (const float*)d_in[2];
    const float* bpt   = (const float*)d_in[3];
    const float* Wpv   = (const float*)d_in[4];
    const float* bpv   = (const float*)d_in[5];
    const float* Ws    = (const float*)d_in[6];
    const float* bs    = (const float*)d_in[7];
    const float* Wproj = (const float*)d_in[8];
    const float* bproj = (const float*)d_in[9];
    const float* Wg    = (const float*)d_in[10];
    const float* al    = (const float*)d_in[11];
    const float* ar    = (const float*)d_in[12];
    const float* Wc    = (const float*)d_in[13];
    const float* bc    = (const float*)d_in[14];
    float* out = (float*)d_out;

    float *ft, *fv, *x, *h, *gat, *Pm, *el, *er, *hgi, *hgt, *part;
    cudaGetSymbolAddress((void**)&ft,  g_feat_t);
    cudaGetSymbolAddress((void**)&fv,  g_feat_v);
    cudaGetSymbolAddress((void**)&x,   g_x);
    cudaGetSymbolAddress((void**)&h,   g_h);
    cudaGetSymbolAddress((void**)&gat, g_gat);
    cudaGetSymbolAddress((void**)&Pm,  g_Pmat);
    cudaGetSymbolAddress((void**)&el,  g_el);
    cudaGetSymbolAddress((void**)&er,  g_er);
    cudaGetSymbolAddress((void**)&hgi, g_hgi);
    cudaGetSymbolAddress((void**)&hgt, g_hgt);
    cudaGetSymbolAddress((void**)&part,g_part);

    const long EMB = (long)Bb * Nn * Cc;

    for (int branch = 0; branch < 2; branch++) {
        const float* Wt = (branch == 0) ? Wpt : Ws;
        const float* bt = (branch == 0) ? bpt : bs;
        const float* Wv = (branch == 0) ? Wpv : Ws;
        const float* bv = (branch == 0) ? bpv : bs;
        float* emb_out = out + (branch == 0 ? 0 : EMB);

        // sigmoid projections
        launch_gemm(utt_t, Wt, bt, ft, Bb * Tt, Hh, Hh, Hh, Hh, Hh, Hh,
                    0, 0, 0, 1, ACT_SIG, 0, 0);
        launch_gemm(utt_v, Wv, bv, fv, Bb * Ii, Hh, Hh, Hh, Hh, Hh, Hh,
                    0, 0, 0, 1, ACT_SIG, 0, 0);

        // relu projection into concatenated x: rows [0,I) = v, [I,N) = t
        launch_gemm(fv, Wproj, bproj, x, Bb * Ii, Pp, Hh, Hh, Hh, Pp, Pp,
                    0, 0, 0, 1, ACT_RELU, Ii, 0);
        launch_gemm(ft, Wproj, bproj, x, Bb * Tt, Pp, Hh, Hh, Hh, Pp, Pp,
                    0, 0, 0, 1, ACT_RELU, Tt, Ii);

        if (branch == 1) {
            mean_kernel<<<dim3(Bb, Pp / 128), 128>>>(x, hgi, 0, Ii);
            mean_kernel<<<dim3(Bb, Pp / 128), 128>>>(x, hgt, Ii, Tt);
        }

        // GAT: h = x @ Wg
        launch_gemm(x, Wg, nullptr, h, Bb * Nn, Gg, Pp, Pp, Pp, Gg, Gg,
                    0, 0, 0, 1, ACT_NONE, 0, 0);
        // el/er scores
        score_kernel<<<Bb * Nn, 128>>>(h, al, ar, el, er);
        // normalized softmax attention matrix (padded to NPAD cols)
        build_p_kernel<<<Bb * Nn, 256>>>(el, er, Pm);
        // batched: gat = elu(P @ h); K padded to 640, B rows guarded at 637
        launch_gemm(Pm, h, nullptr, gat, Nn, Gg, NPAD, Nn, NPAD, Gg, Gg,
                    (long)Nn * NPAD, (long)Nn * Gg, (long)Nn * Gg, Bb,
                    ACT_ELU, 0, 0);
        // emb = gat @ Wc + bc -> directly into output
        launch_gemm(gat, Wc, bc, emb_out, Bb * Nn, Cc, Gg, Gg, Gg, Cc, Cc,
                    0, 0, 0, 1, ACT_NONE, 0, 0);
    }

    // share_loss = sym_kl(hg_i, hg_t) over [B, P]
    kl_kernel<<<Bb, 128>>>(hgi, (long)Pp, hgt, (long)Pp, Pp, part);
    kl_final<<<1, 32>>>(part, out + 2 * EMB);

    // graph_loss = sym_kl(share_emb[:,0,:], private_emb[:,0,:]) over [B, C]
    kl_kernel<<<Bb, 128>>>(out + EMB, (long)Nn * Cc, out, (long)Nn * Cc, Cc, part);
    kl_final<<<1, 32>>>(part, out + 2 * EMB + 1);
}

// round 5
// speedup vs baseline: 3.5531x; 1.0006x over previous
#include <cuda_runtime.h>
#include <math.h>
#include <stdint.h>

// Problem constants
#define Bb 32
#define Tt 60
#define Ii 577
#define Hh 768
#define Pp 384
#define Gg 256
#define Cc 128
#define Nn 637    // Ii + Tt
#define NPAD 640  // Nn padded for guard-free K loop

// ---------------------------------------------------------------------------
// Scratch (static __device__ globals; no allocation anywhere)
// ---------------------------------------------------------------------------
__device__ float g_feat_t[(size_t)Bb * Tt * Hh];
__device__ float g_feat_v[(size_t)Bb * Ii * Hh];
__device__ float g_x[(size_t)Bb * Nn * Pp];
__device__ float g_h[(size_t)Bb * Nn * Gg];
__device__ float g_gat[(size_t)Bb * Nn * Gg];
__device__ float g_Pmat[(size_t)Bb * Nn * NPAD];   // pad cols 637..639 = 0
__device__ float g_el[Bb * Nn];
__device__ float g_er[Bb * Nn];
__device__ float g_hgi[Bb * Pp];
__device__ float g_hgt[Bb * Pp];
__device__ float g_part[2 * Bb];

#define ACT_NONE 0
#define ACT_SIG  1
#define ACT_RELU 2
#define ACT_ELU  3

// ---------------------------------------------------------------------------
// TF32 mma.sync GEMM: 128x128x16 block, 256 threads (8 warps, 2x4),
// warp tile 64x32, m16n8k8 fragments, double-buffered smem.
// Requirements: K % 16 == 0, N % 128 == 0, pointers 16B aligned.
// Kb <= K: B rows in [Kb, K) read as zero (K-padding guard).
// rowsPer > 0 remaps output row r -> (r/rowsPer)*Nn + rowOff + r%rowsPer.
// ---------------------------------------------------------------------------
#define BM 128
#define BN 128
#define BK 16
#define LDA (BK + 4)    // 20 floats  -> conflict-free A-frag reads
#define LDB (BN + 8)    // 136 floats -> conflict-free B-frag reads

__device__ __forceinline__ float cvt_tf32(float x) {
    uint32_t u;
    asm("cvt.rna.tf32.f32 %0, %1;" : "=r"(u) : "f"(x));
    return __uint_as_float(u);
}

__device__ __forceinline__ void mma_tf32(float* c, const uint32_t* a, const uint32_t* b) {
    asm volatile(
        "mma.sync.aligned.m16n8k8.row.col.f32.tf32.tf32.f32 "
        "{%0,%1,%2,%3}, {%4,%5,%6,%7}, {%8,%9}, {%0,%1,%2,%3};"
        : "+f"(c[0]), "+f"(c[1]), "+f"(c[2]), "+f"(c[3])
        : "r"(a[0]), "r"(a[1]), "r"(a[2]), "r"(a[3]), "r"(b[0]), "r"(b[1]));
}

__global__ __launch_bounds__(256, 2) void mma_gemm(
    const float* __restrict__ A, const float* __restrict__ Bm,
    const float* __restrict__ bias, float* __restrict__ C,
    int M, int N, int K, int Kb, int lda, int ldb, int ldc,
    long sA, long sB, long sC,
    int mode, int rowsPer, int rowOff)
{
    A  += (long)blockIdx.z * sA;
    Bm += (long)blockIdx.z * sB;
    C  += (long)blockIdx.z * sC;

    __shared__ float As[2][BM][LDA];   // [m][k] row-major, padded
    __shared__ float Bs[2][BK][LDB];   // [k][n] row-major, padded

    const int tid  = threadIdx.x;
    const int lane = tid & 31;
    const int warp = tid >> 5;
    const int wr   = warp >> 2;        // 0..1 -> 64-row slab
    const int wc   = warp & 3;         // 0..3 -> 32-col slab
    const int g    = lane >> 2;        // groupID 0..7
    const int tg   = lane & 3;         // threadID_in_group 0..3

    const int row0 = blockIdx.y * BM;
    const int col0 = blockIdx.x * BN;

    // gmem loader mapping: A -> 2 float4/thread, B -> 2 float4/thread
    const int ar = tid >> 2, ac = (tid & 3) << 2;           // A: row 0..63(+64), col group
    const int br = tid >> 5, bc = (tid & 31) << 2;          // B: row 0..7(+8), col group

    const float4 z4 = make_float4(0.f, 0.f, 0.f, 0.f);
    float acc[4][4][4] = {};

    const int nTiles = K / BK;

    // ---- load tile helper (macro-free, inlined twice) ----
    float4 aR[2], bR[2];
    {
        // tile 0
        #pragma unroll
        for (int i = 0; i < 2; i++) {
            int r = ar + i * 64;
            aR[i] = (row0 + r < M) ? *(const float4*)(A + (long)(row0 + r) * lda + ac) : z4;
            int kr = br + i * 8;
            bR[i] = (kr < Kb) ? *(const float4*)(Bm + (long)kr * ldb + col0 + bc) : z4;
        }
        #pragma unroll
        for (int i = 0; i < 2; i++) {
            float4 v = aR[i];
            v.x = cvt_tf32(v.x); v.y = cvt_tf32(v.y); v.z = cvt_tf32(v.z); v.w = cvt_tf32(v.w);
            *(float4*)&As[0][ar + i * 64][ac] = v;
            float4 w = bR[i];
            w.x = cvt_tf32(w.x); w.y = cvt_tf32(w.y); w.z = cvt_tf32(w.z); w.w = cvt_tf32(w.w);
            *(float4*)&Bs[0][br + i * 8][bc] = w;
        }
    }
    __syncthreads();

    for (int t = 0; t < nTiles; t++) {
        const int cur = t & 1, nxt = cur ^ 1;
        if (t + 1 < nTiles) {
            const int k0 = (t + 1) * BK;
            #pragma unroll
            for (int i = 0; i < 2; i++) {
                int r = ar + i * 64;
                aR[i] = (row0 + r < M) ? *(const float4*)(A + (long)(row0 + r) * lda + k0 + ac) : z4;
                int kr = k0 + br + i * 8;
                bR[i] = (kr < Kb) ? *(const float4*)(Bm + (long)kr * ldb + col0 + bc) : z4;
            }
        }

        #pragma unroll
        for (int ks = 0; ks < 2; ks++) {
            const int k0 = ks * 8;
            uint32_t bf[4][2];
            #pragma unroll
            for (int ni = 0; ni < 4; ni++) {
                int n = wc * 32 + ni * 8 + g;
                bf[ni][0] = __float_as_uint(Bs[cur][k0 + tg][n]);
                bf[ni][1] = __float_as_uint(Bs[cur][k0 + 4 + tg][n]);
            }
            #pragma unroll
            for (int mi = 0; mi < 4; mi++) {
                int m = wr * 64 + mi * 16 + g;
                uint32_t af[4];
                af[0] = __float_as_uint(As[cur][m][k0 + tg]);
                af[1] = __float_as_uint(As[cur][m + 8][k0 + tg]);
                af[2] = __float_as_uint(As[cur][m][k0 + 4 + tg]);
                af[3] = __float_as_uint(As[cur][m + 8][k0 + 4 + tg]);
                #pragma unroll
                for (int ni = 0; ni < 4; ni++)
                    mma_tf32(acc[mi][ni], af, bf[ni]);
            }
        }

        if (t + 1 < nTiles) {
            #pragma unroll
            for (int i = 0; i < 2; i++) {
                float4 v = aR[i];
                v.x = cvt_tf32(v.x); v.y = cvt_tf32(v.y); v.z = cvt_tf32(v.z); v.w = cvt_tf32(v.w);
                *(float4*)&As[nxt][ar + i * 64][ac] = v;
                float4 w = bR[i];
                w.x = cvt_tf32(w.x); w.y = cvt_tf32(w.y); w.z = cvt_tf32(w.z); w.w = cvt_tf32(w.w);
                *(float4*)&Bs[nxt][br + i * 8][bc] = w;
            }
        }
        __syncthreads();
    }

    // ---- epilogue: bias + activation + optional row remap, float2 stores ----
    #pragma unroll
    for (int mi = 0; mi < 4; mi++) {
        #pragma unroll
        for (int half = 0; half < 2; half++) {
            int r = row0 + wr * 64 + mi * 16 + g + half * 8;
            if (r >= M) continue;
            long orow = r;
            if (rowsPer > 0) orow = (long)(r / rowsPer) * Nn + rowOff + (r % rowsPer);
            float* cbase = C + orow * (long)ldc;
            #pragma unroll
            for (int ni = 0; ni < 4; ni++) {
                int col = col0 + wc * 32 + ni * 8 + 2 * tg;
                float v0 = acc[mi][ni][half * 2 + 0];
                float v1 = acc[mi][ni][half * 2 + 1];
                if (bias) { v0 += bias[col]; v1 += bias[col + 1]; }
                if (mode == ACT_SIG) {
                    v0 = 1.f / (1.f + expf(-v0));
                    v1 = 1.f / (1.f + expf(-v1));
                } else if (mode == ACT_RELU) {
                    v0 = fmaxf(v0, 0.f); v1 = fmaxf(v1, 0.f);
                } else if (mode == ACT_ELU) {
                    v0 = v0 > 0.f ? v0 : expm1f(v0);
                    v1 = v1 > 0.f ? v1 : expm1f(v1);
                }
                *(float2*)(cbase + col) = make_float2(v0, v1);
            }
        }
    }
}

// ---------------------------------------------------------------------------
// Per-row scores: el[row] = h[row,:] . al,  er[row] = h[row,:] . ar  (G=256)
// ---------------------------------------------------------------------------
__global__ void score_kernel(const float* __restrict__ h,
                             const float* __restrict__ al,
                             const float* __restrict__ ar,
                             float* __restrict__ el, float* __restrict__ er)
{
    int row = blockIdx.x;
    const float* hr = h + (long)row * Gg;
    int t = threadIdx.x;   // 128
    float a = hr[t] * al[t] + hr[t + 128] * al[t + 128];
    float b = hr[t] * ar[t] + hr[t + 128] * ar[t + 128];
    __shared__ float sa[128], sb[128];
    sa[t] = a; sb[t] = b; __syncthreads();
    for (int o = 64; o > 0; o >>= 1) {
        if (t < o) { sa[t] += sa[t + o]; sb[t] += sb[t + o]; }
        __syncthreads();
    }
    if (t == 0) { el[row] = sa[0]; er[row] = sb[0]; }
}

// ---------------------------------------------------------------------------
// Build normalized attention matrix into padded rows (ld = NPAD)
// ---------------------------------------------------------------------------
__global__ void build_p_kernel(const float* __restrict__ el,
                               const float* __restrict__ er,
                               float* __restrict__ Pm)
{
    int row = blockIdx.x;              // b*Nn + d
    int b = row / Nn, d = row % Nn;
    const float* elb = el + b * Nn;
    float erd = er[row];
    float* pr = Pm + (long)row * NPAD;
    int t = threadIdx.x;               // 256

    float vals[3];
    float s = 0.f;
    #pragma unroll
    for (int it = 0; it < 3; it++) {
        int sIdx = t + it * 256;
        float v = 0.f;
        if (sIdx < Nn && sIdx != d) {
            float x = elb[sIdx] + erd;
            x = x > 0.f ? x : 0.2f * x;    // leaky relu slope 0.2
            v = expf(x);
        }
        vals[it] = v;
        s += v;
    }
    __shared__ float red[256];
    red[t] = s; __syncthreads();
    for (int o = 128; o > 0; o >>= 1) {
        if (t < o) red[t] += red[t + o];
        __syncthreads();
    }
    float inv = 1.f / red[0];
    #pragma unroll
    for (int it = 0; it < 3; it++) {
        int sIdx = t + it * 256;
        if (sIdx < NPAD) pr[sIdx] = vals[it] * inv;   // pad cols get 0
    }
}

// ---------------------------------------------------------------------------
// Column means over rows [rowOff, rowOff+cnt) of each batch sample
// ---------------------------------------------------------------------------
__global__ void mean_kernel(const float* __restrict__ x, float* __restrict__ out,
                            int rowOff, int cnt)
{
    int b = blockIdx.x;
    int p = blockIdx.y * 128 + threadIdx.x;
    const float* base = x + ((long)b * Nn + rowOff) * Pp + p;
    float s = 0.f;
    for (int i = 0; i < cnt; i++) s += base[(long)i * Pp];
    out[b * Pp + p] = s / (float)cnt;
}

// ---------------------------------------------------------------------------
// Symmetric KL partials per batch row (exact fp32 log-softmax)
// ---------------------------------------------------------------------------
__global__ void kl_kernel(const float* __restrict__ Pm, long sp,
                          const float* __restrict__ Qm, long sq,
                          int D, float* __restrict__ part)
{
    int b = blockIdx.x;
    const float* p = Pm + b * sp;
    const float* q = Qm + b * sq;
    int t = threadIdx.x;   // 128
    __shared__ float s1[128], s2[128];

    float mp = -1e30f, mq = -1e30f;
    for (int c = t; c < D; c += 128) { mp = fmaxf(mp, p[c]); mq = fmaxf(mq, q[c]); }
    s1[t] = mp; s2[t] = mq; __syncthreads();
    for (int o = 64; o > 0; o >>= 1) {
        if (t < o) { s1[t] = fmaxf(s1[t], s1[t + o]); s2[t] = fmaxf(s2[t], s2[t + o]); }
        __syncthreads();
    }
    float MP = s1[0], MQ = s2[0];
    __syncthreads();

    float ssp = 0.f, ssq = 0.f;
    for (int c = t; c < D; c += 128) { ssp += expf(p[c] - MP); ssq += expf(q[c] - MQ); }
    s1[t] = ssp; s2[t] = ssq; __syncthreads();
    for (int o = 64; o > 0; o >>= 1) {
        if (t < o) { s1[t] += s1[t + o]; s2[t] += s2[t + o]; }
        __syncthreads();
    }
    float lsep = MP + logf(s1[0]);
    float lseq = MQ + logf(s2[0]);
    __syncthreads();

    float kpq = 0.f, kqp = 0.f;
    for (int c = t; c < D; c += 128) {
        float lp = p[c] - lsep, lq = q[c] - lseq;
        kpq += expf(lq) * (lq - lp);
        kqp += expf(lp) * (lp - lq);
    }
    s1[t] = kpq; s2[t] = kqp; __syncthreads();
    for (int o = 64; o > 0; o >>= 1) {
        if (t < o) { s1[t] += s1[t + o]; s2[t] += s2[t + o]; }
        __syncthreads();
    }
    if (t == 0) { part[b] = s1[0]; part[Bb + b] = s2[0]; }
}

__global__ void kl_final(const float* __restrict__ part, float* __restrict__ out)
{
    int t = threadIdx.x;   // 32
    float a = part[t], b = part[Bb + t];
    for (int o = 16; o > 0; o >>= 1) {
        a += __shfl_down_sync(0xffffffff, a, o);
        b += __shfl_down_sync(0xffffffff, b, o);
    }
    if (t == 0) out[0] = 0.5f * (a + b);
}

// ---------------------------------------------------------------------------
// Host launch
// ---------------------------------------------------------------------------
static inline void launch_gemm(const float* A, const float* B, const float* bias,
                               float* C, int M, int N, int K, int Kb,
                               int lda, int ldb, int ldc,
                               long sA, long sB, long sC, int batches,
                               int mode, int rowsPer, int rowOff)
{
    dim3 grid(N / BN, (M + BM - 1) / BM, batches);
    mma_gemm<<<grid, 256>>>(A, B, bias, C, M, N, K, Kb, lda, ldb, ldc,
                            sA, sB, sC, mode, rowsPer, rowOff);
}

extern "C" void kernel_launch(void* const* d_in, const int* in_sizes, int n_in,
                              void* d_out, int out_size)
{
    const float* utt_t = (const float*)d_in[0];
    const float* utt_v = (const float*)d_in[1];
    const float* Wpt   = (const float*)d_in[2];
    const float* bpt   = (const float*)d_in[3];
    const float* Wpv   = (const float*)d_in[4];
    const float* bpv   = (const float*)d_in[5];
    const float* Ws    = (const float*)d_in[6];
    const float* bs    = (const float*)d_in[7];
    const float* Wproj = (const float*)d_in[8];
    const float* bproj = (const float*)d_in[9];
    const float* Wg    = (const float*)d_in[10];
    const float* al    = (const float*)d_in[11];
    const float* ar    = (const float*)d_in[12];
    const float* Wc    = (const float*)d_in[13];
    const float* bc    = (const float*)d_in[14];
    float* out = (float*)d_out;

    float *ft, *fv, *x, *h, *gat, *Pm, *el, *er, *hgi, *hgt, *part;
    cudaGetSymbolAddress((void**)&ft,  g_feat_t);
    cudaGetSymbolAddress((void**)&fv,  g_feat_v);
    cudaGetSymbolAddress((void**)&x,   g_x);
    cudaGetSymbolAddress((void**)&h,   g_h);
    cudaGetSymbolAddress((void**)&gat, g_gat);
    cudaGetSymbolAddress((void**)&Pm,  g_Pmat);
    cudaGetSymbolAddress((void**)&el,  g_el);
    cudaGetSymbolAddress((void**)&er,  g_er);
    cudaGetSymbolAddress((void**)&hgi, g_hgi);
    cudaGetSymbolAddress((void**)&hgt, g_hgt);
    cudaGetSymbolAddress((void**)&part,g_part);

    const long EMB = (long)Bb * Nn * Cc;

    for (int branch = 0; branch < 2; branch++) {
        const float* Wt = (branch == 0) ? Wpt : Ws;
        const float* bt = (branch == 0) ? bpt : bs;
        const float* Wv = (branch == 0) ? Wpv : Ws;
        const float* bv = (branch == 0) ? bpv : bs;
        float* emb_out = out + (branch == 0 ? 0 : EMB);

        // sigmoid projections
        launch_gemm(utt_t, Wt, bt, ft, Bb * Tt, Hh, Hh, Hh, Hh, Hh, Hh,
                    0, 0, 0, 1, ACT_SIG, 0, 0);
        launch_gemm(utt_v, Wv, bv, fv, Bb * Ii, Hh, Hh, Hh, Hh, Hh, Hh,
                    0, 0, 0, 1, ACT_SIG, 0, 0);

        // relu projection into concatenated x: rows [0,I) = v, [I,N) = t
        launch_gemm(fv, Wproj, bproj, x, Bb * Ii, Pp, Hh, Hh, Hh, Pp, Pp,
                    0, 0, 0, 1, ACT_RELU, Ii, 0);
        launch_gemm(ft, Wproj, bproj, x, Bb * Tt, Pp, Hh, Hh, Hh, Pp, Pp,
                    0, 0, 0, 1, ACT_RELU, Tt, Ii);

        if (branch == 1) {
            mean_kernel<<<dim3(Bb, Pp / 128), 128>>>(x, hgi, 0, Ii);
            mean_kernel<<<dim3(Bb, Pp / 128), 128>>>(x, hgt, Ii, Tt);
        }

        // GAT: h = x @ Wg
        launch_gemm(x, Wg, nullptr, h, Bb * Nn, Gg, Pp, Pp, Pp, Gg, Gg,
                    0, 0, 0, 1, ACT_NONE, 0, 0);
        // el/er scores
        score_kernel<<<Bb * Nn, 128>>>(h, al, ar, el, er);
        // normalized softmax attention matrix (padded to NPAD cols)
        build_p_kernel<<<Bb * Nn, 256>>>(el, er, Pm);
        // batched: gat = elu(P @ h); K padded to 640, B rows guarded at 637
        launch_gemm(Pm, h, nullptr, gat, Nn, Gg, NPAD, Nn, NPAD, Gg, Gg,
                    (long)Nn * NPAD, (long)Nn * Gg, (long)Nn * Gg, Bb,
                    ACT_ELU, 0, 0);
        // emb = gat @ Wc + bc -> directly into output
        launch_gemm(gat, Wc, bc, emb_out, Bb * Nn, Cc, Gg, Gg, Gg, Cc, Cc,
                    0, 0, 0, 1, ACT_NONE, 0, 0);
    }

    // share_loss = sym_kl(hg_i, hg_t) over [B, P]
    kl_kernel<<<Bb, 128>>>(hgi, (long)Pp, hgt, (long)Pp, Pp, part);
    kl_final<<<1, 32>>>(part, out + 2 * EMB);

    // graph_loss = sym_kl(share_emb[:,0,:], private_emb[:,0,:]) over [B, C]
    kl_kernel<<<Bb, 128>>>(out + EMB, (long)Nn * Cc, out, (long)Nn * Cc, Cc, part);
    kl_final<<<1, 32>>>(part, out + 2 * EMB + 1);
}

// round 6
// speedup vs baseline: 4.0129x; 1.1294x over previous
#include <cuda_runtime.h>
#include <math.h>
#include <stdint.h>

// Problem constants
#define Bb 32
#define Tt 60
#define Ii 577
#define Hh 768
#define Pp 384
#define Gg 256
#define Cc 128
#define Nn 637    // Ii + Tt
#define NPAD 640  // Nn padded for guard-free K loop

// ---------------------------------------------------------------------------
// Scratch: double-buffered per branch (0 = private, 1 = share)
// ---------------------------------------------------------------------------
__device__ float g_feat_t[2][(size_t)Bb * Tt * Hh];
__device__ float g_feat_v[2][(size_t)Bb * Ii * Hh];
__device__ float g_x[2][(size_t)Bb * Nn * Pp];
__device__ float g_h[2][(size_t)Bb * Nn * Gg];
__device__ float g_gat[2][(size_t)Bb * Nn * Gg];
__device__ float g_Pmat[2][(size_t)Bb * Nn * NPAD];
__device__ float g_el[2][Bb * Nn];
__device__ float g_er[2][Bb * Nn];
__device__ float g_hgi[Bb * Pp];
__device__ float g_hgt[Bb * Pp];
__device__ float g_part[2 * Bb];

#define ACT_NONE 0
#define ACT_SIG  1
#define ACT_RELU 2
#define ACT_ELU  3

// ---------------------------------------------------------------------------
// TF32 mma.sync GEMM with DUAL pointer sets batched on blockIdx.z:
//   z <  z0 : set 0 (A0/B0/bias0/C0), zi = z
//   z >= z0 : set 1 (A1/B1/bias1/C1), zi = z - z0
// 128x128x16 block, 256 threads (8 warps 2x4), warp tile 64x32, m16n8k8.
// K % 16 == 0, N % 128 == 0. Kb: B rows in [Kb,K) read as zero.
// rowsPer > 0 remaps output row r -> (r/rowsPer)*Nn + rowOff + r%rowsPer.
// ---------------------------------------------------------------------------
#define BM 128
#define BN 128
#define BK 16
#define LDA (BK + 4)
#define LDB (BN + 8)

__device__ __forceinline__ float cvt_tf32(float x) {
    uint32_t u;
    asm("cvt.rna.tf32.f32 %0, %1;" : "=r"(u) : "f"(x));
    return __uint_as_float(u);
}

__device__ __forceinline__ void mma_tf32(float* c, const uint32_t* a, const uint32_t* b) {
    asm volatile(
        "mma.sync.aligned.m16n8k8.row.col.f32.tf32.tf32.f32 "
        "{%0,%1,%2,%3}, {%4,%5,%6,%7}, {%8,%9}, {%0,%1,%2,%3};"
        : "+f"(c[0]), "+f"(c[1]), "+f"(c[2]), "+f"(c[3])
        : "r"(a[0]), "r"(a[1]), "r"(a[2]), "r"(a[3]), "r"(b[0]), "r"(b[1]));
}

__global__ __launch_bounds__(256, 2) void mma_gemm(
    const float* __restrict__ A0, const float* __restrict__ B0,
    const float* __restrict__ bias0, float* __restrict__ C0,
    const float* __restrict__ A1, const float* __restrict__ B1,
    const float* __restrict__ bias1, float* __restrict__ C1,
    int z0,
    int M, int N, int K, int Kb, int lda, int ldb, int ldc,
    long sA, long sB, long sC,
    int mode, int rowsPer, int rowOff)
{
    const int z = blockIdx.z;
    const float* A    = (z < z0) ? A0    : A1;
    const float* Bm   = (z < z0) ? B0    : B1;
    const float* bias = (z < z0) ? bias0 : bias1;
    float*       C    = (z < z0) ? C0    : C1;
    const long   zi   = (z < z0) ? z     : (z - z0);
    A  += zi * sA;
    Bm += zi * sB;
    C  += zi * sC;

    __shared__ float As[2][BM][LDA];
    __shared__ float Bs[2][BK][LDB];

    const int tid  = threadIdx.x;
    const int lane = tid & 31;
    const int warp = tid >> 5;
    const int wr   = warp >> 2;
    const int wc   = warp & 3;
    const int g    = lane >> 2;
    const int tg   = lane & 3;

    const int row0 = blockIdx.y * BM;
    const int col0 = blockIdx.x * BN;

    const int ar = tid >> 2, ac = (tid & 3) << 2;
    const int br = tid >> 5, bc = (tid & 31) << 2;

    const float4 z4 = make_float4(0.f, 0.f, 0.f, 0.f);
    float acc[4][4][4] = {};

    const int nTiles = K / BK;

    float4 aR[2], bR[2];
    {
        #pragma unroll
        for (int i = 0; i < 2; i++) {
            int r = ar + i * 64;
            aR[i] = (row0 + r < M) ? *(const float4*)(A + (long)(row0 + r) * lda + ac) : z4;
            int kr = br + i * 8;
            bR[i] = (kr < Kb) ? *(const float4*)(Bm + (long)kr * ldb + col0 + bc) : z4;
        }
        #pragma unroll
        for (int i = 0; i < 2; i++) {
            float4 v = aR[i];
            v.x = cvt_tf32(v.x); v.y = cvt_tf32(v.y); v.z = cvt_tf32(v.z); v.w = cvt_tf32(v.w);
            *(float4*)&As[0][ar + i * 64][ac] = v;
            float4 w = bR[i];
            w.x = cvt_tf32(w.x); w.y = cvt_tf32(w.y); w.z = cvt_tf32(w.z); w.w = cvt_tf32(w.w);
            *(float4*)&Bs[0][br + i * 8][bc] = w;
        }
    }
    __syncthreads();

    for (int t = 0; t < nTiles; t++) {
        const int cur = t & 1, nxt = cur ^ 1;
        if (t + 1 < nTiles) {
            const int k0 = (t + 1) * BK;
            #pragma unroll
            for (int i = 0; i < 2; i++) {
                int r = ar + i * 64;
                aR[i] = (row0 + r < M) ? *(const float4*)(A + (long)(row0 + r) * lda + k0 + ac) : z4;
                int kr = k0 + br + i * 8;
                bR[i] = (kr < Kb) ? *(const float4*)(Bm + (long)kr * ldb + col0 + bc) : z4;
            }
        }

        #pragma unroll
        for (int ks = 0; ks < 2; ks++) {
            const int k0 = ks * 8;
            uint32_t bf[4][2];
            #pragma unroll
            for (int ni = 0; ni < 4; ni++) {
                int n = wc * 32 + ni * 8 + g;
                bf[ni][0] = __float_as_uint(Bs[cur][k0 + tg][n]);
                bf[ni][1] = __float_as_uint(Bs[cur][k0 + 4 + tg][n]);
            }
            #pragma unroll
            for (int mi = 0; mi < 4; mi++) {
                int m = wr * 64 + mi * 16 + g;
                uint32_t af[4];
                af[0] = __float_as_uint(As[cur][m][k0 + tg]);
                af[1] = __float_as_uint(As[cur][m + 8][k0 + tg]);
                af[2] = __float_as_uint(As[cur][m][k0 + 4 + tg]);
                af[3] = __float_as_uint(As[cur][m + 8][k0 + 4 + tg]);
                #pragma unroll
                for (int ni = 0; ni < 4; ni++)
                    mma_tf32(acc[mi][ni], af, bf[ni]);
            }
        }

        if (t + 1 < nTiles) {
            #pragma unroll
            for (int i = 0; i < 2; i++) {
                float4 v = aR[i];
                v.x = cvt_tf32(v.x); v.y = cvt_tf32(v.y); v.z = cvt_tf32(v.z); v.w = cvt_tf32(v.w);
                *(float4*)&As[nxt][ar + i * 64][ac] = v;
                float4 w = bR[i];
                w.x = cvt_tf32(w.x); w.y = cvt_tf32(w.y); w.z = cvt_tf32(w.z); w.w = cvt_tf32(w.w);
                *(float4*)&Bs[nxt][br + i * 8][bc] = w;
            }
        }
        __syncthreads();
    }

    #pragma unroll
    for (int mi = 0; mi < 4; mi++) {
        #pragma unroll
        for (int half = 0; half < 2; half++) {
            int r = row0 + wr * 64 + mi * 16 + g + half * 8;
            if (r >= M) continue;
            long orow = r;
            if (rowsPer > 0) orow = (long)(r / rowsPer) * Nn + rowOff + (r % rowsPer);
            float* cbase = C + orow * (long)ldc;
            #pragma unroll
            for (int ni = 0; ni < 4; ni++) {
                int col = col0 + wc * 32 + ni * 8 + 2 * tg;
                float v0 = acc[mi][ni][half * 2 + 0];
                float v1 = acc[mi][ni][half * 2 + 1];
                if (bias) { v0 += bias[col]; v1 += bias[col + 1]; }
                if (mode == ACT_SIG) {
                    v0 = 1.f / (1.f + expf(-v0));
                    v1 = 1.f / (1.f + expf(-v1));
                } else if (mode == ACT_RELU) {
                    v0 = fmaxf(v0, 0.f); v1 = fmaxf(v1, 0.f);
                } else if (mode == ACT_ELU) {
                    v0 = v0 > 0.f ? v0 : expm1f(v0);
                    v1 = v1 > 0.f ? v1 : expm1f(v1);
                }
                *(float2*)(cbase + col) = make_float2(v0, v1);
            }
        }
    }
}

// ---------------------------------------------------------------------------
// Scores for both branches: grid.y = branch
// ---------------------------------------------------------------------------
__global__ void score_kernel(const float* __restrict__ h0,
                             const float* __restrict__ h1,
                             const float* __restrict__ al,
                             const float* __restrict__ ar,
                             float* __restrict__ el, float* __restrict__ er)
{
    int br = blockIdx.y;
    int row = blockIdx.x;
    const float* h = (br == 0) ? h0 : h1;
    const float* hr = h + (long)row * Gg;
    int t = threadIdx.x;   // 128
    float a = hr[t] * al[t] + hr[t + 128] * al[t + 128];
    float b = hr[t] * ar[t] + hr[t + 128] * ar[t + 128];
    __shared__ float sa[128], sb[128];
    sa[t] = a; sb[t] = b; __syncthreads();
    for (int o = 64; o > 0; o >>= 1) {
        if (t < o) { sa[t] += sa[t + o]; sb[t] += sb[t + o]; }
        __syncthreads();
    }
    if (t == 0) {
        el[br * (Bb * Nn) + row] = sa[0];
        er[br * (Bb * Nn) + row] = sb[0];
    }
}

// ---------------------------------------------------------------------------
// Build normalized attention matrices for both branches: grid.y = branch
// ---------------------------------------------------------------------------
__global__ void build_p_kernel(const float* __restrict__ el,
                               const float* __restrict__ er,
                               float* __restrict__ P0, float* __restrict__ P1)
{
    int brn = blockIdx.y;
    int row = blockIdx.x;              // b*Nn + d
    int b = row / Nn, d = row % Nn;
    const float* elb = el + brn * (Bb * Nn) + b * Nn;
    float erd = er[brn * (Bb * Nn) + row];
    float* pr = ((brn == 0) ? P0 : P1) + (long)row * NPAD;
    int t = threadIdx.x;               // 256

    float vals[3];
    float s = 0.f;
    #pragma unroll
    for (int it = 0; it < 3; it++) {
        int sIdx = t + it * 256;
        float v = 0.f;
        if (sIdx < Nn && sIdx != d) {
            float x = elb[sIdx] + erd;
            x = x > 0.f ? x : 0.2f * x;
            v = expf(x);
        }
        vals[it] = v;
        s += v;
    }
    __shared__ float red[256];
    red[t] = s; __syncthreads();
    for (int o = 128; o > 0; o >>= 1) {
        if (t < o) red[t] += red[t + o];
        __syncthreads();
    }
    float inv = 1.f / red[0];
    #pragma unroll
    for (int it = 0; it < 3; it++) {
        int sIdx = t + it * 256;
        if (sIdx < NPAD) pr[sIdx] = vals[it] * inv;
    }
}

// ---------------------------------------------------------------------------
// Column means: grid.z selects (v -> hgi) or (t -> hgt) readout
// ---------------------------------------------------------------------------
__global__ void mean_kernel(const float* __restrict__ x,
                            float* __restrict__ hgi, float* __restrict__ hgt)
{
    int which = blockIdx.z;
    int rowOff = which ? Ii : 0;
    int cnt    = which ? Tt : Ii;
    float* out = which ? hgt : hgi;
    int b = blockIdx.x;
    int p = blockIdx.y * 128 + threadIdx.x;
    const float* base = x + ((long)b * Nn + rowOff) * Pp + p;
    float s = 0.f;
    for (int i = 0; i < cnt; i++) s += base[(long)i * Pp];
    out[b * Pp + p] = s / (float)cnt;
}

// ---------------------------------------------------------------------------
// Symmetric KL partials per batch row (exact fp32 log-softmax)
// ---------------------------------------------------------------------------
__global__ void kl_kernel(const float* __restrict__ Pm, long sp,
                          const float* __restrict__ Qm, long sq,
                          int D, float* __restrict__ part)
{
    int b = blockIdx.x;
    const float* p = Pm + b * sp;
    const float* q = Qm + b * sq;
    int t = threadIdx.x;   // 128
    __shared__ float s1[128], s2[128];

    float mp = -1e30f, mq = -1e30f;
    for (int c = t; c < D; c += 128) { mp = fmaxf(mp, p[c]); mq = fmaxf(mq, q[c]); }
    s1[t] = mp; s2[t] = mq; __syncthreads();
    for (int o = 64; o > 0; o >>= 1) {
        if (t < o) { s1[t] = fmaxf(s1[t], s1[t + o]); s2[t] = fmaxf(s2[t], s2[t + o]); }
        __syncthreads();
    }
    float MP = s1[0], MQ = s2[0];
    __syncthreads();

    float ssp = 0.f, ssq = 0.f;
    for (int c = t; c < D; c += 128) { ssp += expf(p[c] - MP); ssq += expf(q[c] - MQ); }
    s1[t] = ssp; s2[t] = ssq; __syncthreads();
    for (int o = 64; o > 0; o >>= 1) {
        if (t < o) { s1[t] += s1[t + o]; s2[t] += s2[t + o]; }
        __syncthreads();
    }
    float lsep = MP + logf(s1[0]);
    float lseq = MQ + logf(s2[0]);
    __syncthreads();

    float kpq = 0.f, kqp = 0.f;
    for (int c = t; c < D; c += 128) {
        float lp = p[c] - lsep, lq = q[c] - lseq;
        kpq += expf(lq) * (lq - lp);
        kqp += expf(lp) * (lp - lq);
    }
    s1[t] = kpq; s2[t] = kqp; __syncthreads();
    for (int o = 64; o > 0; o >>= 1) {
        if (t < o) { s1[t] += s1[t + o]; s2[t] += s2[t + o]; }
        __syncthreads();
    }
    if (t == 0) { part[b] = s1[0]; part[Bb + b] = s2[0]; }
}

__global__ void kl_final(const float* __restrict__ part, float* __restrict__ out)
{
    int t = threadIdx.x;   // 32
    float a = part[t], b = part[Bb + t];
    for (int o = 16; o > 0; o >>= 1) {
        a += __shfl_down_sync(0xffffffff, a, o);
        b += __shfl_down_sync(0xffffffff, b, o);
    }
    if (t == 0) out[0] = 0.5f * (a + b);
}

// ---------------------------------------------------------------------------
// Host launch
// ---------------------------------------------------------------------------
static inline void launch_gemm2(
    const float* A0, const float* B0, const float* b0, float* C0,
    const float* A1, const float* B1, const float* b1, float* C1,
    int z0, int z1,
    int M, int N, int K, int Kb, int lda, int ldb, int ldc,
    long sA, long sB, long sC,
    int mode, int rowsPer, int rowOff)
{
    dim3 grid(N / BN, (M + BM - 1) / BM, z0 + z1);
    mma_gemm<<<grid, 256>>>(A0, B0, b0, C0, A1, B1, b1, C1, z0,
                            M, N, K, Kb, lda, ldb, ldc, sA, sB, sC,
                            mode, rowsPer, rowOff);
}

extern "C" void kernel_launch(void* const* d_in, const int* in_sizes, int n_in,
                              void* d_out, int out_size)
{
    const float* utt_t = (const float*)d_in[0];
    const float* utt_v = (const float*)d_in[1];
    const float* Wpt   = (const float*)d_in[2];
    const float* bpt   = (const float*)d_in[3];
    const float* Wpv   = (const float*)d_in[4];
    const float* bpv   = (const float*)d_in[5];
    const float* Ws    = (const float*)d_in[6];
    const float* bs    = (const float*)d_in[7];
    const float* Wproj = (const float*)d_in[8];
    const float* bproj = (const float*)d_in[9];
    const float* Wg    = (const float*)d_in[10];
    const float* al    = (const float*)d_in[11];
    const float* ar    = (const float*)d_in[12];
    const float* Wc    = (const float*)d_in[13];
    const float* bc    = (const float*)d_in[14];
    float* out = (float*)d_out;

    float *ft0, *ft1, *fv0, *fv1, *x0, *x1, *h0, *h1, *gat0, *gat1;
    float *Pm0, *Pm1, *el, *er, *hgi, *hgt, *part;
    cudaGetSymbolAddress((void**)&ft0, g_feat_t);
    cudaGetSymbolAddress((void**)&fv0, g_feat_v);
    cudaGetSymbolAddress((void**)&x0,  g_x);
    cudaGetSymbolAddress((void**)&h0,  g_h);
    cudaGetSymbolAddress((void**)&gat0,g_gat);
    cudaGetSymbolAddress((void**)&Pm0, g_Pmat);
    cudaGetSymbolAddress((void**)&el,  g_el);
    cudaGetSymbolAddress((void**)&er,  g_er);
    cudaGetSymbolAddress((void**)&hgi, g_hgi);
    cudaGetSymbolAddress((void**)&hgt, g_hgt);
    cudaGetSymbolAddress((void**)&part,g_part);
    ft1  = ft0  + (size_t)Bb * Tt * Hh;
    fv1  = fv0  + (size_t)Bb * Ii * Hh;
    x1   = x0   + (size_t)Bb * Nn * Pp;
    h1   = h0   + (size_t)Bb * Nn * Gg;
    gat1 = gat0 + (size_t)Bb * Nn * Gg;
    Pm1  = Pm0  + (size_t)Bb * Nn * NPAD;

    const long EMB = (long)Bb * Nn * Cc;

    // L1: sigmoid projections, both branches per launch
    launch_gemm2(utt_t, Wpt, bpt, ft0, utt_t, Ws, bs, ft1, 1, 1,
                 Bb * Tt, Hh, Hh, Hh, Hh, Hh, Hh, 0, 0, 0, ACT_SIG, 0, 0);
    launch_gemm2(utt_v, Wpv, bpv, fv0, utt_v, Ws, bs, fv1, 1, 1,
                 Bb * Ii, Hh, Hh, Hh, Hh, Hh, Hh, 0, 0, 0, ACT_SIG, 0, 0);

    // L2: relu projections into concatenated x (rows [0,I)=v, [I,N)=t)
    launch_gemm2(fv0, Wproj, bproj, x0, fv1, Wproj, bproj, x1, 1, 1,
                 Bb * Ii, Pp, Hh, Hh, Hh, Pp, Pp, 0, 0, 0, ACT_RELU, Ii, 0);
    launch_gemm2(ft0, Wproj, bproj, x0, ft1, Wproj, bproj, x1, 1, 1,
                 Bb * Tt, Pp, Hh, Hh, Hh, Pp, Pp, 0, 0, 0, ACT_RELU, Tt, Ii);

    // share-branch readout means (depends only on x1)
    mean_kernel<<<dim3(Bb, Pp / 128, 2), 128>>>(x1, hgi, hgt);

    // L3: h = x @ Wg (both branches)
    launch_gemm2(x0, Wg, nullptr, h0, x1, Wg, nullptr, h1, 1, 1,
                 Bb * Nn, Gg, Pp, Pp, Pp, Gg, Gg, 0, 0, 0, ACT_NONE, 0, 0);

    // L4: scores, both branches
    score_kernel<<<dim3(Bb * Nn, 2), 128>>>(h0, h1, al, ar, el, er);

    // L5: attention matrices, both branches
    build_p_kernel<<<dim3(Bb * Nn, 2), 256>>>(el, er, Pm0, Pm1);

    // L6: gat = elu(P @ h), batched over 2*Bb samples
    launch_gemm2(Pm0, h0, nullptr, gat0, Pm1, h1, nullptr, gat1, Bb, Bb,
                 Nn, Gg, NPAD, Nn, NPAD, Gg, Gg,
                 (long)Nn * NPAD, (long)Nn * Gg, (long)Nn * Gg,
                 ACT_ELU, 0, 0);

    // L7: emb = gat @ Wc + bc -> straight into output
    launch_gemm2(gat0, Wc, bc, out, gat1, Wc, bc, out + EMB, 1, 1,
                 Bb * Nn, Cc, Gg, Gg, Gg, Cc, Cc, 0, 0, 0, ACT_NONE, 0, 0);

    // share_loss = sym_kl(hg_i, hg_t) over [B, P]
    kl_kernel<<<Bb, 128>>>(hgi, (long)Pp, hgt, (long)Pp, Pp, part);
    kl_final<<<1, 32>>>(part, out + 2 * EMB);

    // graph_loss = sym_kl(share_emb[:,0,:], private_emb[:,0,:]) over [B, C]
    kl_kernel<<<Bb, 128>>>(out + EMB, (long)Nn * Cc, out, (long)Nn * Cc, Cc, part);
    kl_final<<<1, 32>>>(part, out + 2 * EMB + 1);
}

// round 7
// speedup vs baseline: 4.8133x; 1.1994x over previous
#include <cuda_runtime.h>
#include <math.h>
#include <stdint.h>

// Problem constants
#define Bb 32
#define Tt 60
#define Ii 577
#define Hh 768
#define Pp 384
#define Gg 256
#define Cc 128
#define Nn 637    // Ii + Tt
#define NPAD 640  // Nn padded for guard-free K loop

// ---------------------------------------------------------------------------
// Rounded-input scratch segments (floats)
// ---------------------------------------------------------------------------
#define SZ_UTT_T  1474560    // 32*60*768
#define SZ_UTT_V  14177280   // 32*577*768
#define SZ_W      589824     // 768*768
#define SZ_WPROJ  294912     // 768*384
#define SZ_WG     98304      // 384*256
#define SZ_WC     32768      // 256*128
#define OFF_UTT_T 0
#define OFF_UTT_V (OFF_UTT_T + SZ_UTT_T)                    // 1474560
#define OFF_WPT   (OFF_UTT_V + SZ_UTT_V)                    // 15651840
#define OFF_WPV   (OFF_WPT + SZ_W)                          // 16241664
#define OFF_WS    (OFF_WPV + SZ_W)                          // 16831488
#define OFF_WPROJ (OFF_WS + SZ_W)                           // 17421312
#define OFF_WG    (OFF_WPROJ + SZ_WPROJ)                    // 17716224
#define OFF_WC    (OFF_WG + SZ_WG)                          // 17814528
#define RND_TOTAL (OFF_WC + SZ_WC)                          // 17847296

__device__ float g_rnd[RND_TOTAL];
__device__ float g_fcat[2][(size_t)Bb * Nn * Hh];
__device__ float g_x[2][(size_t)Bb * Nn * Pp];
__device__ float g_h[2][(size_t)Bb * Nn * Gg];
__device__ float g_gat[2][(size_t)Bb * Nn * Gg];
__device__ float g_Pmat[2][(size_t)Bb * Nn * NPAD];
__device__ float g_el[2][Bb * Nn];
__device__ float g_er[2][Bb * Nn];
__device__ float g_hgi[Bb * Pp];
__device__ float g_hgt[Bb * Pp];
__device__ float g_part[2 * Bb];

#define ACT_NONE 0
#define ACT_SIG  1
#define ACT_RELU 2
#define ACT_ELU  3
#define ACT_RND  4   // OR-flag: tf32-round stored output

__device__ __forceinline__ float cvt_tf32(float x) {
    uint32_t u;
    asm("cvt.rna.tf32.f32 %0, %1;" : "=r"(u) : "f"(x));
    return __uint_as_float(u);
}

__device__ __forceinline__ void mma_tf32(float* c, const uint32_t* a, const uint32_t* b) {
    asm volatile(
        "mma.sync.aligned.m16n8k8.row.col.f32.tf32.tf32.f32 "
        "{%0,%1,%2,%3}, {%4,%5,%6,%7}, {%8,%9}, {%0,%1,%2,%3};"
        : "+f"(c[0]), "+f"(c[1]), "+f"(c[2]), "+f"(c[3])
        : "r"(a[0]), "r"(a[1]), "r"(a[2]), "r"(a[3]), "r"(b[0]), "r"(b[1]));
}

__device__ __forceinline__ void cp16(uint32_t dst, const void* src, bool pred) {
    int sz = pred ? 16 : 0;
    asm volatile("cp.async.cg.shared.global [%0], [%1], 16, %2;\n"
                 :: "r"(dst), "l"(src), "r"(sz));
}

// ---------------------------------------------------------------------------
// Multi-set TF32 GEMM, cp.async 3-stage pipeline.
// 128x128x16 block, 256 threads (8 warps 2x4), warp tile 64x32, m16n8k8.
// Up to 4 pointer sets selected by blockIdx.z ranges (zEnd cumulative).
// All inputs must be pre-rounded to tf32. K % 16 == 0, N % 128 == 0.
// Kb: B rows in [Kb, K) read as zero. Per-set M with row guard + early exit.
// rowsPer > 0 remaps output row r -> (r/rowsPer)*Nn + rowOff + r%rowsPer.
// ---------------------------------------------------------------------------
#define BM 128
#define BN 128
#define BK 16
#define LDA 20
#define LDB 136
#define STAGES 3
#define ASTAGE (BM * LDA)                 // 2560 floats
#define BSTAGE (BK * LDB)                 // 2176 floats
#define SM_FLOATS (STAGES * (ASTAGE + BSTAGE))  // 14208 floats = 56832 B

struct GSet {
    const float* A; const float* B; const float* bias; float* C;
    int M; int rowsPer; int rowOff;
};
struct GArgs {
    GSet s[4];
    int zEnd[4];
    int nSets;
    int N, K, Kb, lda, ldb, ldc;
    long sA, sB, sC;
    int mode;
};

__global__ __launch_bounds__(256, 2) void mma_gemm(GArgs ga)
{
    // resolve pointer set from z
    int z = blockIdx.z;
    int si = 0;
    while (si < ga.nSets - 1 && z >= ga.zEnd[si]) si++;
    const int zStart = (si == 0) ? 0 : ga.zEnd[si - 1];
    const GSet st = ga.s[si];
    const int M = st.M;
    const int row0 = blockIdx.y * BM;
    if (row0 >= M) return;                 // uniform early exit (unused tile)
    const long zi = z - zStart;
    const float* A  = st.A + zi * ga.sA;
    const float* Bm = st.B + zi * ga.sB;
    float*       C  = st.C + zi * ga.sC;

    const int lda = ga.lda, ldb = ga.ldb, Kb = ga.Kb;
    const int col0 = blockIdx.x * BN;

    extern __shared__ float sm[];
    float* AsBase = sm;
    float* BsBase = sm + STAGES * ASTAGE;
    const uint32_t smAddr = (uint32_t)__cvta_generic_to_shared(sm);

    const int tid  = threadIdx.x;
    const int lane = tid & 31;
    const int warp = tid >> 5;
    const int wr   = warp >> 2;
    const int wc   = warp & 3;
    const int g    = lane >> 2;
    const int tg   = lane & 3;

    // loader lane mapping
    const int ar = tid >> 1, ac = (tid & 1) * 8;   // A: row, 8-float col group
    const int br = tid >> 5, bc = (tid & 31) * 4;  // B: k-row, 4-float col group
    const bool pa = (row0 + ar) < M;
    const float* aSrc = A + (long)(row0 + (pa ? ar : 0)) * lda + ac;
    const float* bSrc = Bm + col0 + bc;

    const int nTiles = ga.K / BK;

    // prologue: stages 0..1
    #pragma unroll
    for (int s = 0; s < STAGES - 1; s++) {
        const int k0 = s * BK;
        uint32_t da = smAddr + (uint32_t)(s * ASTAGE + ar * LDA + ac) * 4;
        cp16(da,      aSrc + k0,     pa);
        cp16(da + 16, aSrc + k0 + 4, pa);
        #pragma unroll
        for (int i = 0; i < 2; i++) {
            int k = br + i * 8;
            bool pb = (k0 + k) < Kb;
            uint32_t db = smAddr + (uint32_t)(STAGES * ASTAGE + s * BSTAGE + k * LDB + bc) * 4;
            cp16(db, bSrc + (long)(k0 + (pb ? k : 0)) * ldb, pb);
        }
        asm volatile("cp.async.commit_group;\n" ::: "memory");
    }

    float acc[4][4][4] = {};

    for (int t = 0; t < nTiles; t++) {
        asm volatile("cp.async.wait_group 1;\n" ::: "memory");
        __syncthreads();

        const int cur = t % STAGES;
        const float* As = AsBase + cur * ASTAGE;
        const float* Bs = BsBase + cur * BSTAGE;

        #pragma unroll
        for (int ks = 0; ks < 2; ks++) {
            const int k0 = ks * 8;
            uint32_t bf[4][2];
            #pragma unroll
            for (int ni = 0; ni < 4; ni++) {
                int n = wc * 32 + ni * 8 + g;
                bf[ni][0] = __float_as_uint(Bs[(k0 + tg) * LDB + n]);
                bf[ni][1] = __float_as_uint(Bs[(k0 + 4 + tg) * LDB + n]);
            }
            #pragma unroll
            for (int mi = 0; mi < 4; mi++) {
                int m = wr * 64 + mi * 16 + g;
                uint32_t af[4];
                af[0] = __float_as_uint(As[m * LDA + k0 + tg]);
                af[1] = __float_as_uint(As[(m + 8) * LDA + k0 + tg]);
                af[2] = __float_as_uint(As[m * LDA + k0 + 4 + tg]);
                af[3] = __float_as_uint(As[(m + 8) * LDA + k0 + 4 + tg]);
                #pragma unroll
                for (int ni = 0; ni < 4; ni++)
                    mma_tf32(acc[mi][ni], af, bf[ni]);
            }
        }

        // issue load for tile t+2 into stage (t+2)%3 (read last at iter t-1;
        // every warp passed the sync above, so it is free)
        const int nt = t + STAGES - 1;
        if (nt < nTiles) {
            const int s = nt % STAGES;
            const int k0 = nt * BK;
            uint32_t da = smAddr + (uint32_t)(s * ASTAGE + ar * LDA + ac) * 4;
            cp16(da,      aSrc + k0,     pa);
            cp16(da + 16, aSrc + k0 + 4, pa);
            #pragma unroll
            for (int i = 0; i < 2; i++) {
                int k = br + i * 8;
                bool pb = (k0 + k) < Kb;
                uint32_t db = smAddr + (uint32_t)(STAGES * ASTAGE + s * BSTAGE + k * LDB + bc) * 4;
                cp16(db, bSrc + (long)(k0 + (pb ? k : 0)) * ldb, pb);
            }
        }
        asm volatile("cp.async.commit_group;\n" ::: "memory");
    }

    // epilogue
    const int act = ga.mode & 3;
    const bool rnd = (ga.mode & ACT_RND) != 0;
    const float* bias = st.bias;
    #pragma unroll
    for (int mi = 0; mi < 4; mi++) {
        #pragma unroll
        for (int half = 0; half < 2; half++) {
            int r = row0 + wr * 64 + mi * 16 + g + half * 8;
            if (r >= M) continue;
            long orow = r;
            if (st.rowsPer > 0)
                orow = (long)(r / st.rowsPer) * Nn + st.rowOff + (r % st.rowsPer);
            float* cbase = C + orow * (long)ga.ldc;
            #pragma unroll
            for (int ni = 0; ni < 4; ni++) {
                int col = col0 + wc * 32 + ni * 8 + 2 * tg;
                float v0 = acc[mi][ni][half * 2 + 0];
                float v1 = acc[mi][ni][half * 2 + 1];
                if (bias) { v0 += bias[col]; v1 += bias[col + 1]; }
                if (act == ACT_SIG) {
                    v0 = 1.f / (1.f + expf(-v0));
                    v1 = 1.f / (1.f + expf(-v1));
                } else if (act == ACT_RELU) {
                    v0 = fmaxf(v0, 0.f); v1 = fmaxf(v1, 0.f);
                } else if (act == ACT_ELU) {
                    v0 = v0 > 0.f ? v0 : expm1f(v0);
                    v1 = v1 > 0.f ? v1 : expm1f(v1);
                }
                if (rnd) { v0 = cvt_tf32(v0); v1 = cvt_tf32(v1); }
                *(float2*)(cbase + col) = make_float2(v0, v1);
            }
        }
    }
}

// ---------------------------------------------------------------------------
// Pre-round inputs + weights to tf32 into g_rnd (float4 grid-stride)
// ---------------------------------------------------------------------------
struct RArgs { const float4* src[8]; };

__global__ void round_kernel(RArgs ra, float4* dst)
{
    // segment boundaries in float4 units
    const int seg[9] = {0, 368640, 3912960, 4060416, 4207872,
                        4355328, 4429056, 4453632, 4461824};
    const int total = 4461824;
    for (int i = blockIdx.x * blockDim.x + threadIdx.x; i < total;
         i += gridDim.x * blockDim.x) {
        int s = 0;
        while (i >= seg[s + 1]) s++;
        float4 v = ra.src[s][i - seg[s]];
        v.x = cvt_tf32(v.x); v.y = cvt_tf32(v.y);
        v.z = cvt_tf32(v.z); v.w = cvt_tf32(v.w);
        dst[i] = v;
    }
}

// ---------------------------------------------------------------------------
// Scores for both branches: grid.y = branch
// ---------------------------------------------------------------------------
__global__ void score_kernel(const float* __restrict__ h0,
                             const float* __restrict__ h1,
                             const float* __restrict__ al,
                             const float* __restrict__ ar,
                             float* __restrict__ el, float* __restrict__ er)
{
    int br = blockIdx.y;
    int row = blockIdx.x;
    const float* h = (br == 0) ? h0 : h1;
    const float* hr = h + (long)row * Gg;
    int t = threadIdx.x;   // 128
    float a = hr[t] * al[t] + hr[t + 128] * al[t + 128];
    float b = hr[t] * ar[t] + hr[t + 128] * ar[t + 128];
    __shared__ float sa[128], sb[128];
    sa[t] = a; sb[t] = b; __syncthreads();
    for (int o = 64; o > 0; o >>= 1) {
        if (t < o) { sa[t] += sa[t + o]; sb[t] += sb[t + o]; }
        __syncthreads();
    }
    if (t == 0) {
        el[br * (Bb * Nn) + row] = sa[0];
        er[br * (Bb * Nn) + row] = sb[0];
    }
}

// ---------------------------------------------------------------------------
// Build normalized attention matrices (tf32-rounded) for both branches
// ---------------------------------------------------------------------------
__global__ void build_p_kernel(const float* __restrict__ el,
                               const float* __restrict__ er,
                               float* __restrict__ P0, float* __restrict__ P1)
{
    int brn = blockIdx.y;
    int row = blockIdx.x;              // b*Nn + d
    int b = row / Nn, d = row % Nn;
    const float* elb = el + brn * (Bb * Nn) + b * Nn;
    float erd = er[brn * (Bb * Nn) + row];
    float* pr = ((brn == 0) ? P0 : P1) + (long)row * NPAD;
    int t = threadIdx.x;               // 256

    float vals[3];
    float s = 0.f;
    #pragma unroll
    for (int it = 0; it < 3; it++) {
        int sIdx = t + it * 256;
        float v = 0.f;
        if (sIdx < Nn && sIdx != d) {
            float x = elb[sIdx] + erd;
            x = x > 0.f ? x : 0.2f * x;
            v = expf(x);
        }
        vals[it] = v;
        s += v;
    }
    __shared__ float red[256];
    red[t] = s; __syncthreads();
    for (int o = 128; o > 0; o >>= 1) {
        if (t < o) red[t] += red[t + o];
        __syncthreads();
    }
    float inv = 1.f / red[0];
    #pragma unroll
    for (int it = 0; it < 3; it++) {
        int sIdx = t + it * 256;
        if (sIdx < NPAD) pr[sIdx] = cvt_tf32(vals[it] * inv);
    }
}

// ---------------------------------------------------------------------------
// Column means: grid.z selects (v -> hgi) or (t -> hgt)
// ---------------------------------------------------------------------------
__global__ void mean_kernel(const float* __restrict__ x,
                            float* __restrict__ hgi, float* __restrict__ hgt)
{
    int which = blockIdx.z;
    int rowOff = which ? Ii : 0;
    int cnt    = which ? Tt : Ii;
    float* out = which ? hgt : hgi;
    int b = blockIdx.x;
    int p = blockIdx.y * 128 + threadIdx.x;
    const float* base = x + ((long)b * Nn + rowOff) * Pp + p;
    float s = 0.f;
    for (int i = 0; i < cnt; i++) s += base[(long)i * Pp];
    out[b * Pp + p] = s / (float)cnt;
}

// ---------------------------------------------------------------------------
// Symmetric KL partials per batch row (exact fp32 log-softmax)
// ---------------------------------------------------------------------------
__global__ void kl_kernel(const float* __restrict__ Pm, long sp,
                          const float* __restrict__ Qm, long sq,
                          int D, float* __restrict__ part)
{
    int b = blockIdx.x;
    const float* p = Pm + b * sp;
    const float* q = Qm + b * sq;
    int t = threadIdx.x;   // 128
    __shared__ float s1[128], s2[128];

    float mp = -1e30f, mq = -1e30f;
    for (int c = t; c < D; c += 128) { mp = fmaxf(mp, p[c]); mq = fmaxf(mq, q[c]); }
    s1[t] = mp; s2[t] = mq; __syncthreads();
    for (int o = 64; o > 0; o >>= 1) {
        if (t < o) { s1[t] = fmaxf(s1[t], s1[t + o]); s2[t] = fmaxf(s2[t], s2[t + o]); }
        __syncthreads();
    }
    float MP = s1[0], MQ = s2[0];
    __syncthreads();

    float ssp = 0.f, ssq = 0.f;
    for (int c = t; c < D; c += 128) { ssp += expf(p[c] - MP); ssq += expf(q[c] - MQ); }
    s1[t] = ssp; s2[t] = ssq; __syncthreads();
    for (int o = 64; o > 0; o >>= 1) {
        if (t < o) { s1[t] += s1[t + o]; s2[t] += s2[t + o]; }
        __syncthreads();
    }
    float lsep = MP + logf(s1[0]);
    float lseq = MQ + logf(s2[0]);
    __syncthreads();

    float kpq = 0.f, kqp = 0.f;
    for (int c = t; c < D; c += 128) {
        float lp = p[c] - lsep, lq = q[c] - lseq;
        kpq += expf(lq) * (lq - lp);
        kqp += expf(lp) * (lp - lq);
    }
    s1[t] = kpq; s2[t] = kqp; __syncthreads();
    for (int o = 64; o > 0; o >>= 1) {
        if (t < o) { s1[t] += s1[t + o]; s2[t] += s2[t + o]; }
        __syncthreads();
    }
    if (t == 0) { part[b] = s1[0]; part[Bb + b] = s2[0]; }
}

__global__ void kl_final(const float* __restrict__ part, float* __restrict__ out)
{
    int t = threadIdx.x;   // 32
    float a = part[t], b = part[Bb + t];
    for (int o = 16; o > 0; o >>= 1) {
        a += __shfl_down_sync(0xffffffff, a, o);
        b += __shfl_down_sync(0xffffffff, b, o);
    }
    if (t == 0) out[0] = 0.5f * (a + b);
}

// ---------------------------------------------------------------------------
// Host launch
// ---------------------------------------------------------------------------
extern "C" void kernel_launch(void* const* d_in, const int* in_sizes, int n_in,
                              void* d_out, int out_size)
{
    const float* utt_t = (const float*)d_in[0];
    const float* utt_v = (const float*)d_in[1];
    const float* Wpt   = (const float*)d_in[2];
    const float* bpt   = (const float*)d_in[3];
    const float* Wpv   = (const float*)d_in[4];
    const float* bpv   = (const float*)d_in[5];
    const float* Ws    = (const float*)d_in[6];
    const float* bs    = (const float*)d_in[7];
    const float* Wproj = (const float*)d_in[8];
    const float* bproj = (const float*)d_in[9];
    const float* Wg    = (const float*)d_in[10];
    const float* al    = (const float*)d_in[11];
    const float* ar    = (const float*)d_in[12];
    const float* Wc    = (const float*)d_in[13];
    const float* bc    = (const float*)d_in[14];
    float* out = (float*)d_out;

    float *rnd, *fcat0, *x0, *h0, *gat0, *Pm0, *el, *er, *hgi, *hgt, *part;
    cudaGetSymbolAddress((void**)&rnd,  g_rnd);
    cudaGetSymbolAddress((void**)&fcat0,g_fcat);
    cudaGetSymbolAddress((void**)&x0,   g_x);
    cudaGetSymbolAddress((void**)&h0,   g_h);
    cudaGetSymbolAddress((void**)&gat0, g_gat);
    cudaGetSymbolAddress((void**)&Pm0,  g_Pmat);
    cudaGetSymbolAddress((void**)&el,   g_el);
    cudaGetSymbolAddress((void**)&er,   g_er);
    cudaGetSymbolAddress((void**)&hgi,  g_hgi);
    cudaGetSymbolAddress((void**)&hgt,  g_hgt);
    cudaGetSymbolAddress((void**)&part, g_part);

    float* fcat1 = fcat0 + (size_t)Bb * Nn * Hh;
    float* x1    = x0    + (size_t)Bb * Nn * Pp;
    float* h1    = h0    + (size_t)Bb * Nn * Gg;
    float* gat1  = gat0  + (size_t)Bb * Nn * Gg;
    float* Pm1   = Pm0   + (size_t)Bb * Nn * NPAD;

    const float* utt_t_r = rnd + OFF_UTT_T;
    const float* utt_v_r = rnd + OFF_UTT_V;
    const float* Wpt_r   = rnd + OFF_WPT;
    const float* Wpv_r   = rnd + OFF_WPV;
    const float* Ws_r    = rnd + OFF_WS;
    const float* Wproj_r = rnd + OFF_WPROJ;
    const float* Wg_r    = rnd + OFF_WG;
    const float* Wc_r    = rnd + OFF_WC;

    const long EMB = (long)Bb * Nn * Cc;
    const size_t smemBytes = SM_FLOATS * sizeof(float);   // 56832

    cudaFuncSetAttribute(mma_gemm,
        cudaFuncAttributeMaxDynamicSharedMemorySize, (int)smemBytes);

    // 0) pre-round inputs + weights
    {
        RArgs ra;
        ra.src[0] = (const float4*)utt_t; ra.src[1] = (const float4*)utt_v;
        ra.src[2] = (const float4*)Wpt;   ra.src[3] = (const float4*)Wpv;
        ra.src[4] = (const float4*)Ws;    ra.src[5] = (const float4*)Wproj;
        ra.src[6] = (const float4*)Wg;    ra.src[7] = (const float4*)Wc;
        round_kernel<<<1184, 256>>>(ra, (float4*)rnd);
    }

    // 1) fused sigmoid layer: 4 sets -> f_cat (v rows [0,Ii), t rows [Ii,Nn))
    {
        GArgs ga = {};
        ga.s[0] = { utt_v_r, Wpv_r, bpv, fcat0, Bb * Ii, Ii, 0 };
        ga.s[1] = { utt_v_r, Ws_r,  bs,  fcat1, Bb * Ii, Ii, 0 };
        ga.s[2] = { utt_t_r, Wpt_r, bpt, fcat0, Bb * Tt, Tt, Ii };
        ga.s[3] = { utt_t_r, Ws_r,  bs,  fcat1, Bb * Tt, Tt, Ii };
        ga.zEnd[0] = 1; ga.zEnd[1] = 2; ga.zEnd[2] = 3; ga.zEnd[3] = 4;
        ga.nSets = 4;
        ga.N = Hh; ga.K = Hh; ga.Kb = Hh; ga.lda = Hh; ga.ldb = Hh; ga.ldc = Hh;
        ga.sA = ga.sB = ga.sC = 0;
        ga.mode = ACT_SIG | ACT_RND;
        dim3 grid(Hh / BN, (Bb * Ii + BM - 1) / BM, 4);
        mma_gemm<<<grid, 256, smemBytes>>>(ga);
    }

    // 2) relu projection on concatenated rows: x = relu(f_cat @ Wproj + b)
    {
        GArgs ga = {};
        ga.s[0] = { fcat0, Wproj_r, bproj, x0, Bb * Nn, 0, 0 };
        ga.s[1] = { fcat1, Wproj_r, bproj, x1, Bb * Nn, 0, 0 };
        ga.zEnd[0] = 1; ga.zEnd[1] = 2; ga.nSets = 2;
        ga.N = Pp; ga.K = Hh; ga.Kb = Hh; ga.lda = Hh; ga.ldb = Pp; ga.ldc = Pp;
        ga.sA = ga.sB = ga.sC = 0;
        ga.mode = ACT_RELU | ACT_RND;
        dim3 grid(Pp / BN, (Bb * Nn + BM - 1) / BM, 2);
        mma_gemm<<<grid, 256, smemBytes>>>(ga);
    }

    // share-branch readout means (x1)
    mean_kernel<<<dim3(Bb, Pp / 128, 2), 128>>>(x1, hgi, hgt);

    // 3) h = x @ Wg
    {
        GArgs ga = {};
        ga.s[0] = { x0, Wg_r, nullptr, h0, Bb * Nn, 0, 0 };
        ga.s[1] = { x1, Wg_r, nullptr, h1, Bb * Nn, 0, 0 };
        ga.zEnd[0] = 1; ga.zEnd[1] = 2; ga.nSets = 2;
        ga.N = Gg; ga.K = Pp; ga.Kb = Pp; ga.lda = Pp; ga.ldb = Gg; ga.ldc = Gg;
        ga.sA = ga.sB = ga.sC = 0;
        ga.mode = ACT_NONE | ACT_RND;
        dim3 grid(Gg / BN, (Bb * Nn + BM - 1) / BM, 2);
        mma_gemm<<<grid, 256, smemBytes>>>(ga);
    }

    // 4) scores + 5) attention matrices (both branches)
    score_kernel<<<dim3(Bb * Nn, 2), 128>>>(h0, h1, al, ar, el, er);
    build_p_kernel<<<dim3(Bb * Nn, 2), 256>>>(el, er, Pm0, Pm1);

    // 6) gat = elu(P @ h), batched 2*Bb samples
    {
        GArgs ga = {};
        ga.s[0] = { Pm0, h0, nullptr, gat0, Nn, 0, 0 };
        ga.s[1] = { Pm1, h1, nullptr, gat1, Nn, 0, 0 };
        ga.zEnd[0] = Bb; ga.zEnd[1] = 2 * Bb; ga.nSets = 2;
        ga.N = Gg; ga.K = NPAD; ga.Kb = Nn;
        ga.lda = NPAD; ga.ldb = Gg; ga.ldc = Gg;
        ga.sA = (long)Nn * NPAD; ga.sB = (long)Nn * Gg; ga.sC = (long)Nn * Gg;
        ga.mode = ACT_ELU | ACT_RND;
        dim3 grid(Gg / BN, (Nn + BM - 1) / BM, 2 * Bb);
        mma_gemm<<<grid, 256, smemBytes>>>(ga);
    }

    // 7) emb = gat @ Wc + bc -> final output (fp32, no rounding)
    {
        GArgs ga = {};
        ga.s[0] = { gat0, Wc_r, bc, out,       Bb * Nn, 0, 0 };
        ga.s[1] = { gat1, Wc_r, bc, out + EMB, Bb * Nn, 0, 0 };
        ga.zEnd[0] = 1; ga.zEnd[1] = 2; ga.nSets = 2;
        ga.N = Cc; ga.K = Gg; ga.Kb = Gg; ga.lda = Gg; ga.ldb = Cc; ga.ldc = Cc;
        ga.sA = ga.sB = ga.sC = 0;
        ga.mode = ACT_NONE;
        dim3 grid(Cc / BN, (Bb * Nn + BM - 1) / BM, 2);
        mma_gemm<<<grid, 256, smemBytes>>>(ga);
    }

    // losses
    kl_kernel<<<Bb, 128>>>(hgi, (long)Pp, hgt, (long)Pp, Pp, part);
    kl_final<<<1, 32>>>(part, out + 2 * EMB);
    kl_kernel<<<Bb, 128>>>(out + EMB, (long)Nn * Cc, out, (long)Nn * Cc, Cc, part);
    kl_final<<<1, 32>>>(part, out + 2 * EMB + 1);
}